// round 1
// baseline (speedup 1.0000x reference)
#include <cuda_runtime.h>
#include <math.h>

// Problem constants (fixed by the reference)
#define NN    100000
#define EE    1600000
#define TOT_E (EE + NN)     // edges + self loops
#define HH    4
#define CC    32
#define DD    128

// ---------------- scratch (device globals: allocation-free) ----------------
__device__ float g_h[NN * DD];        // x @ W          [N,128]
__device__ float g_skip[NN * DD];     // x @ skip_W     [N,128]
__device__ float g_agg[NN * DD];      // message accumulator
__device__ float g_as[NN * HH];       // per-node src logits
__device__ float g_ad[NN * HH];       // per-node dst logits
__device__ float g_m[NN * HH];        // segment max
__device__ float g_z[NN * HH];        // segment sum of exp
__device__ float g_e[TOT_E * HH];     // per-edge e, then p (reused)
__device__ int   g_is64;              // edge_index dtype flag

// ---------------- helpers ----------------
__device__ __forceinline__ void atomicMaxF(float* a, float v) {
    if (v >= 0.0f) atomicMax((int*)a, __float_as_int(v));
    else           atomicMin((unsigned int*)a, __float_as_uint(v));
}

__device__ __forceinline__ void red_add_v4(float* p, float a, float b, float c, float d) {
    asm volatile("red.global.add.v4.f32 [%0], {%1,%2,%3,%4};"
                 :: "l"(p), "f"(a), "f"(b), "f"(c), "f"(d) : "memory");
}

__device__ __forceinline__ void load_edge(const void* ei, int i, int& s, int& d) {
    if (g_is64) {
        const long long* p = (const long long*)ei;
        s = (int)p[i]; d = (int)p[EE + i];
    } else {
        const int* p = (const int*)ei;
        s = p[i]; d = p[EE + i];
    }
}

__device__ __forceinline__ float lrelu(float v) { return v > 0.0f ? v : 0.2f * v; }

// ---------------- kernels ----------------

// Probe whether edge_index arrived as int64 or int32.
// If int32, reading pairs as int64 yields values >= 2^32 (hi half is another
// random index, nonzero w.p. ~1-1e-5 each over 64 samples).
__global__ void detect_k(const long long* ei) {
    if (blockIdx.x == 0 && threadIdx.x == 0) {
        int ok64 = 1;
        for (int i = 0; i < 64; i++) {
            long long v = ei[i];
            if (v < 0 || v >= NN) { ok64 = 0; break; }
        }
        g_is64 = ok64;
    }
}

__global__ void init_k() {
    int i = blockIdx.x * blockDim.x + threadIdx.x;
    if (i < NN * DD) g_agg[i] = 0.0f;
    if (i < NN * HH) {
        g_m[i] = __int_as_float(0xff800000);  // -inf
        g_z[i] = 0.0f;
    }
}

// Fused GEMM: [N,128] x [128,256] -> g_h (cols 0..127), g_skip (cols 128..255)
// Block: 64 rows x 256 cols, 256 threads, 4x16 microtile per thread.
__global__ void __launch_bounds__(256) gemm_k(const float* __restrict__ x,
                                              const float* __restrict__ W,
                                              const float* __restrict__ sW) {
    __shared__ float xs[64 * 33];   // [64 rows][32 k], padded
    __shared__ float ws[32 * 256];  // [32 k][256 cols]
    int t  = threadIdx.x;
    int m0 = blockIdx.x * 64;
    int tm = t >> 4, tn = t & 15;

    float acc[4][16];
#pragma unroll
    for (int r = 0; r < 4; r++)
#pragma unroll
        for (int j = 0; j < 16; j++) acc[r][j] = 0.0f;

    for (int kk = 0; kk < 128; kk += 32) {
        __syncthreads();
        // weights: 8192 floats = 2048 float4 -> 8 per thread
#pragma unroll
        for (int i = 0; i < 8; i++) {
            int fi = i * 256 + t;           // float4 index
            int r  = fi >> 6;               // k row 0..31
            int c  = (fi & 63) * 4;         // col 0..255
            const float* src = (c < 128) ? (W + (kk + r) * 128 + c)
                                         : (sW + (kk + r) * 128 + (c - 128));
            ((float4*)ws)[fi] = *(const float4*)src;
        }
        // x tile: 64x32 = 2048 floats = 512 float4 -> 2 per thread
#pragma unroll
        for (int i = 0; i < 2; i++) {
            int fi  = i * 256 + t;
            int r   = fi >> 3;
            int c4  = (fi & 7) * 4;
            int row = m0 + r;
            float4 v = make_float4(0.f, 0.f, 0.f, 0.f);
            if (row < NN) v = *(const float4*)(x + row * 128 + kk + c4);
            xs[r * 33 + c4 + 0] = v.x;
            xs[r * 33 + c4 + 1] = v.y;
            xs[r * 33 + c4 + 2] = v.z;
            xs[r * 33 + c4 + 3] = v.w;
        }
        __syncthreads();

#pragma unroll
        for (int k = 0; k < 32; k++) {
            const float4* wr = (const float4*)(ws + k * 256 + tn * 16);
            float4 w0 = wr[0], w1 = wr[1], w2 = wr[2], w3 = wr[3];
            float a0 = xs[(tm * 4 + 0) * 33 + k];
            float a1 = xs[(tm * 4 + 1) * 33 + k];
            float a2 = xs[(tm * 4 + 2) * 33 + k];
            float a3 = xs[(tm * 4 + 3) * 33 + k];
            float av[4] = {a0, a1, a2, a3};
#pragma unroll
            for (int r = 0; r < 4; r++) {
                acc[r][0]  += av[r] * w0.x; acc[r][1]  += av[r] * w0.y;
                acc[r][2]  += av[r] * w0.z; acc[r][3]  += av[r] * w0.w;
                acc[r][4]  += av[r] * w1.x; acc[r][5]  += av[r] * w1.y;
                acc[r][6]  += av[r] * w1.z; acc[r][7]  += av[r] * w1.w;
                acc[r][8]  += av[r] * w2.x; acc[r][9]  += av[r] * w2.y;
                acc[r][10] += av[r] * w2.z; acc[r][11] += av[r] * w2.w;
                acc[r][12] += av[r] * w3.x; acc[r][13] += av[r] * w3.y;
                acc[r][14] += av[r] * w3.z; acc[r][15] += av[r] * w3.w;
            }
        }
    }

    int cb = tn * 16;
#pragma unroll
    for (int r = 0; r < 4; r++) {
        int row = m0 + tm * 4 + r;
        if (row >= NN) continue;
        float* dst = (cb < 128) ? (g_h + row * 128 + cb)
                                : (g_skip + row * 128 + (cb - 128));
#pragma unroll
        for (int j = 0; j < 4; j++) {
            float4 v = make_float4(acc[r][4 * j], acc[r][4 * j + 1],
                                   acc[r][4 * j + 2], acc[r][4 * j + 3]);
            ((float4*)dst)[j] = v;
        }
    }
}

// warp per node: a_s[n,h] = dot(h[n, h*32:(h+1)*32], att_src[h]); same for dst
__global__ void att_k(const float* __restrict__ asrc, const float* __restrict__ adst) {
    int g = blockIdx.x * blockDim.x + threadIdx.x;
    int n = g >> 5, lane = g & 31;
    if (n >= NN) return;
    float4 hv = ((const float4*)(g_h + n * 128))[lane];
    float4 vs = ((const float4*)asrc)[lane];
    float4 vd = ((const float4*)adst)[lane];
    float ps = hv.x * vs.x + hv.y * vs.y + hv.z * vs.z + hv.w * vs.w;
    float pd = hv.x * vd.x + hv.y * vd.y + hv.z * vd.z + hv.w * vd.w;
#pragma unroll
    for (int o = 4; o >= 1; o >>= 1) {
        ps += __shfl_down_sync(0xffffffff, ps, o);
        pd += __shfl_down_sync(0xffffffff, pd, o);
    }
    if ((lane & 7) == 0) {
        int h = lane >> 3;
        g_as[n * 4 + h] = ps;
        g_ad[n * 4 + h] = pd;
    }
}

// pass 1: e = lrelu(a_s[src]+a_d[dst]); segment max into g_m
__global__ void emax_k(const void* __restrict__ ei) {
    int i = blockIdx.x * blockDim.x + threadIdx.x;
    if (i >= TOT_E) return;
    int s, d;
    if (i < EE) load_edge(ei, i, s, d); else s = d = i - EE;
    float4 as = *(const float4*)(g_as + s * 4);
    float4 ad = *(const float4*)(g_ad + d * 4);
    float4 e;
    e.x = lrelu(as.x + ad.x); e.y = lrelu(as.y + ad.y);
    e.z = lrelu(as.z + ad.z); e.w = lrelu(as.w + ad.w);
    *(float4*)(g_e + i * 4) = e;
    atomicMaxF(&g_m[d * 4 + 0], e.x);
    atomicMaxF(&g_m[d * 4 + 1], e.y);
    atomicMaxF(&g_m[d * 4 + 2], e.z);
    atomicMaxF(&g_m[d * 4 + 3], e.w);
}

// pass 2: p = exp(e - m[dst]); segment sum into g_z; store p
__global__ void esum_k(const void* __restrict__ ei) {
    int i = blockIdx.x * blockDim.x + threadIdx.x;
    if (i >= TOT_E) return;
    int s, d;
    if (i < EE) load_edge(ei, i, s, d); else s = d = i - EE;
    float4 e = *(const float4*)(g_e + i * 4);
    float4 m = *(const float4*)(g_m + d * 4);
    float4 p;
    p.x = expf(e.x - m.x); p.y = expf(e.y - m.y);
    p.z = expf(e.z - m.z); p.w = expf(e.w - m.w);
    *(float4*)(g_e + i * 4) = p;
    red_add_v4(g_z + d * 4, p.x, p.y, p.z, p.w);
}

// pass 3: warp per edge; agg[dst] += h[src] * alpha
__global__ void eagg_k(const void* __restrict__ ei) {
    int g = blockIdx.x * blockDim.x + threadIdx.x;
    int i = g >> 5, lane = g & 31;
    if (i >= TOT_E) return;
    int s, d;
    if (i < EE) load_edge(ei, i, s, d); else s = d = i - EE;
    float4 p = *(const float4*)(g_e + i * 4);
    float4 z = *(const float4*)(g_z + d * 4);
    int h = lane >> 3;  // cols lane*4..lane*4+3 all in head lane/8
    float ph = (h == 0) ? p.x : (h == 1) ? p.y : (h == 2) ? p.z : p.w;
    float zh = (h == 0) ? z.x : (h == 1) ? z.y : (h == 2) ? z.z : z.w;
    float alpha = ph / (zh + 1e-16f);
    float4 hv = ((const float4*)(g_h + (size_t)s * 128))[lane];
    float* dst = g_agg + (size_t)d * 128 + lane * 4;
    red_add_v4(dst, hv.x * alpha, hv.y * alpha, hv.z * alpha, hv.w * alpha);
}

// epilogue: warp per node; bias + skip + layernorm
__global__ void final_k(const float* __restrict__ gb, const float* __restrict__ sb,
                        const float* __restrict__ lg, const float* __restrict__ lb,
                        float* __restrict__ out) {
    int g = blockIdx.x * blockDim.x + threadIdx.x;
    int n = g >> 5, lane = g & 31;
    if (n >= NN) return;
    float4 v  = ((const float4*)(g_agg + n * 128))[lane];
    float4 sk = ((const float4*)(g_skip + n * 128))[lane];
    float4 b1 = ((const float4*)gb)[lane];
    float4 b2 = ((const float4*)sb)[lane];
    v.x += sk.x + b1.x + b2.x;
    v.y += sk.y + b1.y + b2.y;
    v.z += sk.z + b1.z + b2.z;
    v.w += sk.w + b1.w + b2.w;
    float sum = v.x + v.y + v.z + v.w;
    float sq  = v.x * v.x + v.y * v.y + v.z * v.z + v.w * v.w;
#pragma unroll
    for (int o = 16; o >= 1; o >>= 1) {
        sum += __shfl_xor_sync(0xffffffff, sum, o);
        sq  += __shfl_xor_sync(0xffffffff, sq, o);
    }
    float mu  = sum * (1.0f / 128.0f);
    float var = sq * (1.0f / 128.0f) - mu * mu;
    float inv = rsqrtf(var + 1e-5f);
    float4 gg = ((const float4*)lg)[lane];
    float4 bb = ((const float4*)lb)[lane];
    float4 o4;
    o4.x = (v.x - mu) * inv * gg.x + bb.x;
    o4.y = (v.y - mu) * inv * gg.y + bb.y;
    o4.z = (v.z - mu) * inv * gg.z + bb.z;
    o4.w = (v.w - mu) * inv * gg.w + bb.w;
    ((float4*)(out + n * 128))[lane] = o4;
}

// ---------------- launch ----------------
extern "C" void kernel_launch(void* const* d_in, const int* in_sizes, int n_in,
                              void* d_out, int out_size) {
    const float* x        = (const float*)d_in[0];
    const void*  ei       = d_in[1];
    const float* W        = (const float*)d_in[2];
    const float* att_src  = (const float*)d_in[3];
    const float* att_dst  = (const float*)d_in[4];
    const float* gat_bias = (const float*)d_in[5];
    const float* skip_W   = (const float*)d_in[6];
    const float* skip_b   = (const float*)d_in[7];
    const float* ln_g     = (const float*)d_in[8];
    const float* ln_b     = (const float*)d_in[9];
    float* out = (float*)d_out;

    detect_k<<<1, 32>>>((const long long*)ei);
    init_k<<<(NN * DD + 255) / 256, 256>>>();
    gemm_k<<<(NN + 63) / 64, 256>>>(x, W, skip_W);
    att_k<<<(NN * 32 + 255) / 256, 256>>>(att_src, att_dst);
    emax_k<<<(TOT_E + 255) / 256, 256>>>(ei);
    esum_k<<<(TOT_E + 255) / 256, 256>>>(ei);
    {
        long long th = (long long)TOT_E * 32;
        eagg_k<<<(unsigned int)((th + 255) / 256), 256>>>(ei);
    }
    final_k<<<(NN * 32 + 255) / 256, 256>>>(gat_bias, skip_b, ln_g, ln_b, out);
}

// round 2
// speedup vs baseline: 1.5186x; 1.5186x over previous
#include <cuda_runtime.h>
#include <math.h>

// Problem constants
#define NN    100000
#define EE    1600000
#define HH    4
#define DD    128

// ---------------- scratch (device globals) ----------------
__device__ float g_h[NN * DD];       // x @ W
__device__ float g_skip[NN * DD];    // x @ skip_W
__device__ float g_as[NN * HH];      // src logits
__device__ float g_ad[NN * HH];      // dst logits
__device__ int   g_cnt[NN];          // in-degree histogram
__device__ int   g_exc[NN];          // per-block exclusive scan
__device__ int   g_bsum[128];        // block sums
__device__ int   g_boff[128];        // block offsets
__device__ int   g_off[NN + 1];      // CSR offsets
__device__ int   g_cur[NN];          // scatter cursors
__device__ int   g_esrc[EE];         // CSR: src node per slot
__device__ int   g_is64;             // edge dtype flag

// ---------------- helpers ----------------
__device__ __forceinline__ float lrelu(float v) { return v > 0.0f ? v : 0.2f * v; }

__device__ __forceinline__ int load_dst(const void* ei, int i) {
    return g_is64 ? (int)((const long long*)ei)[EE + i] : ((const int*)ei)[EE + i];
}
__device__ __forceinline__ void load_edge(const void* ei, int i, int& s, int& d) {
    if (g_is64) {
        const long long* p = (const long long*)ei;
        s = (int)p[i]; d = (int)p[EE + i];
    } else {
        const int* p = (const int*)ei;
        s = p[i]; d = p[EE + i];
    }
}

// ---------------- kernels ----------------
__global__ void detect_k(const long long* ei) {
    if (blockIdx.x == 0 && threadIdx.x == 0) {
        int ok64 = 1;
        for (int i = 0; i < 64; i++) {
            long long v = ei[i];
            if (v < 0 || v >= NN) { ok64 = 0; break; }
        }
        g_is64 = ok64;
    }
}

__global__ void init_k() {
    int i = blockIdx.x * blockDim.x + threadIdx.x;
    if (i < NN) g_cnt[i] = 0;
}

__global__ void hist_k(const void* __restrict__ ei) {
    int i = blockIdx.x * blockDim.x + threadIdx.x;
    if (i >= EE) return;
    atomicAdd(&g_cnt[load_dst(ei, i)], 1);
}

// block-level exclusive scan (1024 elems/block)
__global__ void __launch_bounds__(1024) scanA_k() {
    __shared__ int sd[1024];
    int t = threadIdx.x;
    int i = blockIdx.x * 1024 + t;
    int v = (i < NN) ? g_cnt[i] : 0;
    sd[t] = v;
    __syncthreads();
#pragma unroll
    for (int o = 1; o < 1024; o <<= 1) {
        int x = (t >= o) ? sd[t - o] : 0;
        __syncthreads();
        sd[t] += x;
        __syncthreads();
    }
    if (i < NN) g_exc[i] = sd[t] - v;
    if (t == 1023) g_bsum[blockIdx.x] = sd[t];
}

__global__ void scanB_k(int nblocks) {
    __shared__ int sd[128];
    int t = threadIdx.x;
    int v = (t < nblocks) ? g_bsum[t] : 0;
    sd[t] = v;
    __syncthreads();
#pragma unroll
    for (int o = 1; o < 128; o <<= 1) {
        int x = (t >= o) ? sd[t - o] : 0;
        __syncthreads();
        sd[t] += x;
        __syncthreads();
    }
    g_boff[t] = sd[t] - v;
}

__global__ void scanC_k() {
    int i = blockIdx.x * blockDim.x + threadIdx.x;
    if (i < NN) {
        int off = g_exc[i] + g_boff[i >> 10];
        g_off[i] = off;
        g_cur[i] = off;
    }
    if (i == 0) g_off[NN] = EE;
}

__global__ void scatter_k(const void* __restrict__ ei) {
    int i = blockIdx.x * blockDim.x + threadIdx.x;
    if (i >= EE) return;
    int s, d;
    load_edge(ei, i, s, d);
    int pos = atomicAdd(&g_cur[d], 1);
    g_esrc[pos] = s;
}

// Fused GEMM: [N,128] x [128,256] -> g_h (cols 0..127), g_skip (cols 128..255)
__global__ void __launch_bounds__(256) gemm_k(const float* __restrict__ x,
                                              const float* __restrict__ W,
                                              const float* __restrict__ sW) {
    __shared__ float xs[64 * 33];
    __shared__ float ws[32 * 256];
    int t  = threadIdx.x;
    int m0 = blockIdx.x * 64;
    int tm = t >> 4, tn = t & 15;

    float acc[4][16];
#pragma unroll
    for (int r = 0; r < 4; r++)
#pragma unroll
        for (int j = 0; j < 16; j++) acc[r][j] = 0.0f;

    for (int kk = 0; kk < 128; kk += 32) {
        __syncthreads();
#pragma unroll
        for (int i = 0; i < 8; i++) {
            int fi = i * 256 + t;
            int r  = fi >> 6;
            int c  = (fi & 63) * 4;
            const float* src = (c < 128) ? (W + (kk + r) * 128 + c)
                                         : (sW + (kk + r) * 128 + (c - 128));
            ((float4*)ws)[fi] = *(const float4*)src;
        }
#pragma unroll
        for (int i = 0; i < 2; i++) {
            int fi  = i * 256 + t;
            int r   = fi >> 3;
            int c4  = (fi & 7) * 4;
            int row = m0 + r;
            float4 v = make_float4(0.f, 0.f, 0.f, 0.f);
            if (row < NN) v = *(const float4*)(x + row * 128 + kk + c4);
            xs[r * 33 + c4 + 0] = v.x;
            xs[r * 33 + c4 + 1] = v.y;
            xs[r * 33 + c4 + 2] = v.z;
            xs[r * 33 + c4 + 3] = v.w;
        }
        __syncthreads();

#pragma unroll
        for (int k = 0; k < 32; k++) {
            const float4* wr = (const float4*)(ws + k * 256 + tn * 16);
            float4 w0 = wr[0], w1 = wr[1], w2 = wr[2], w3 = wr[3];
            float av[4];
#pragma unroll
            for (int r = 0; r < 4; r++) av[r] = xs[(tm * 4 + r) * 33 + k];
#pragma unroll
            for (int r = 0; r < 4; r++) {
                acc[r][0]  += av[r] * w0.x; acc[r][1]  += av[r] * w0.y;
                acc[r][2]  += av[r] * w0.z; acc[r][3]  += av[r] * w0.w;
                acc[r][4]  += av[r] * w1.x; acc[r][5]  += av[r] * w1.y;
                acc[r][6]  += av[r] * w1.z; acc[r][7]  += av[r] * w1.w;
                acc[r][8]  += av[r] * w2.x; acc[r][9]  += av[r] * w2.y;
                acc[r][10] += av[r] * w2.z; acc[r][11] += av[r] * w2.w;
                acc[r][12] += av[r] * w3.x; acc[r][13] += av[r] * w3.y;
                acc[r][14] += av[r] * w3.z; acc[r][15] += av[r] * w3.w;
            }
        }
    }

    int cb = tn * 16;
#pragma unroll
    for (int r = 0; r < 4; r++) {
        int row = m0 + tm * 4 + r;
        if (row >= NN) continue;
        float* dst = (cb < 128) ? (g_h + row * 128 + cb)
                                : (g_skip + row * 128 + (cb - 128));
#pragma unroll
        for (int j = 0; j < 4; j++) {
            float4 v = make_float4(acc[r][4 * j], acc[r][4 * j + 1],
                                   acc[r][4 * j + 2], acc[r][4 * j + 3]);
            ((float4*)dst)[j] = v;
        }
    }
}

// warp per node: per-head logits
__global__ void att_k(const float* __restrict__ asrc, const float* __restrict__ adst) {
    int g = blockIdx.x * blockDim.x + threadIdx.x;
    int n = g >> 5, lane = g & 31;
    if (n >= NN) return;
    float4 hv = ((const float4*)(g_h + n * 128))[lane];
    float4 vs = ((const float4*)asrc)[lane];
    float4 vd = ((const float4*)adst)[lane];
    float ps = hv.x * vs.x + hv.y * vs.y + hv.z * vs.z + hv.w * vs.w;
    float pd = hv.x * vd.x + hv.y * vd.y + hv.z * vd.z + hv.w * vd.w;
#pragma unroll
    for (int o = 4; o >= 1; o >>= 1) {
        ps += __shfl_down_sync(0xffffffff, ps, o);
        pd += __shfl_down_sync(0xffffffff, pd, o);
    }
    if ((lane & 7) == 0) {
        int h = lane >> 3;
        g_as[n * 4 + h] = ps;
        g_ad[n * 4 + h] = pd;
    }
}

// Fused: CSR aggregation + inline softmax-normalization + bias + skip + LayerNorm
// warp per dst node; lane owns channels lane*4..lane*4+3 (head = lane>>3)
__global__ void __launch_bounds__(256) eagg_k(const float* __restrict__ gb,
                                              const float* __restrict__ sb,
                                              const float* __restrict__ lg,
                                              const float* __restrict__ lb,
                                              float* __restrict__ out) {
    int g = blockIdx.x * blockDim.x + threadIdx.x;
    int n = g >> 5, lane = g & 31;
    if (n >= NN) return;
    int h = lane >> 3;

    float ad_h = g_ad[n * 4 + h];

    // self-loop contribution
    float as_self = g_as[n * 4 + h];
    float p = __expf(lrelu(as_self + ad_h));
    float4 hv = ((const float4*)(g_h + (size_t)n * 128))[lane];
    float z = p;
    float4 acc;
    acc.x = p * hv.x; acc.y = p * hv.y; acc.z = p * hv.z; acc.w = p * hv.w;

    int e   = g_off[n];
    int end = g_off[n + 1];
    for (; e + 1 < end; e += 2) {
        int s0 = g_esrc[e];
        int s1 = g_esrc[e + 1];
        float a0 = __ldg(g_as + s0 * 4 + h);
        float a1 = __ldg(g_as + s1 * 4 + h);
        float4 h0 = ((const float4*)(g_h + (size_t)s0 * 128))[lane];
        float4 h1 = ((const float4*)(g_h + (size_t)s1 * 128))[lane];
        float p0 = __expf(lrelu(a0 + ad_h));
        float p1 = __expf(lrelu(a1 + ad_h));
        z += p0 + p1;
        acc.x += p0 * h0.x + p1 * h1.x;
        acc.y += p0 * h0.y + p1 * h1.y;
        acc.z += p0 * h0.z + p1 * h1.z;
        acc.w += p0 * h0.w + p1 * h1.w;
    }
    if (e < end) {
        int s0 = g_esrc[e];
        float a0 = __ldg(g_as + s0 * 4 + h);
        float4 h0 = ((const float4*)(g_h + (size_t)s0 * 128))[lane];
        float p0 = __expf(lrelu(a0 + ad_h));
        z += p0;
        acc.x += p0 * h0.x;
        acc.y += p0 * h0.y;
        acc.z += p0 * h0.z;
        acc.w += p0 * h0.w;
    }

    float inv = 1.0f / (z + 1e-16f);
    float4 sk = ((const float4*)(g_skip + (size_t)n * 128))[lane];
    float4 b1 = ((const float4*)gb)[lane];
    float4 b2 = ((const float4*)sb)[lane];
    float4 v;
    v.x = acc.x * inv + sk.x + b1.x + b2.x;
    v.y = acc.y * inv + sk.y + b1.y + b2.y;
    v.z = acc.z * inv + sk.z + b1.z + b2.z;
    v.w = acc.w * inv + sk.w + b1.w + b2.w;

    float sum = v.x + v.y + v.z + v.w;
    float sq  = v.x * v.x + v.y * v.y + v.z * v.z + v.w * v.w;
#pragma unroll
    for (int o = 16; o >= 1; o >>= 1) {
        sum += __shfl_xor_sync(0xffffffff, sum, o);
        sq  += __shfl_xor_sync(0xffffffff, sq, o);
    }
    float mu  = sum * (1.0f / 128.0f);
    float var = sq * (1.0f / 128.0f) - mu * mu;
    float invs = rsqrtf(var + 1e-5f);
    float4 gg = ((const float4*)lg)[lane];
    float4 bb = ((const float4*)lb)[lane];
    float4 o4;
    o4.x = (v.x - mu) * invs * gg.x + bb.x;
    o4.y = (v.y - mu) * invs * gg.y + bb.y;
    o4.z = (v.z - mu) * invs * gg.z + bb.z;
    o4.w = (v.w - mu) * invs * gg.w + bb.w;
    ((float4*)(out + (size_t)n * 128))[lane] = o4;
}

// ---------------- launch ----------------
extern "C" void kernel_launch(void* const* d_in, const int* in_sizes, int n_in,
                              void* d_out, int out_size) {
    const float* x        = (const float*)d_in[0];
    const void*  ei       = d_in[1];
    const float* W        = (const float*)d_in[2];
    const float* att_src  = (const float*)d_in[3];
    const float* att_dst  = (const float*)d_in[4];
    const float* gat_bias = (const float*)d_in[5];
    const float* skip_W   = (const float*)d_in[6];
    const float* skip_b   = (const float*)d_in[7];
    const float* ln_g     = (const float*)d_in[8];
    const float* ln_b     = (const float*)d_in[9];
    float* out = (float*)d_out;

    int nblocks = (NN + 1023) / 1024;  // 98

    detect_k<<<1, 32>>>((const long long*)ei);                    // 0
    init_k<<<(NN + 255) / 256, 256>>>();                          // 1
    hist_k<<<(EE + 255) / 256, 256>>>(ei);                        // 2
    scanA_k<<<nblocks, 1024>>>();                                 // 3
    scanB_k<<<1, 128>>>(nblocks);                                 // 4
    gemm_k<<<(NN + 63) / 64, 256>>>(x, W, skip_W);                // 5  <- ncu slot
    scanC_k<<<(NN + 255) / 256, 256>>>();                         // 6
    scatter_k<<<(EE + 255) / 256, 256>>>(ei);                     // 7
    att_k<<<(NN * 32 + 255) / 256, 256>>>(att_src, att_dst);      // 8
    eagg_k<<<(NN * 32 + 255) / 256, 256>>>(gat_bias, skip_b,      // 9
                                           ln_g, ln_b, out);
}

// round 4
// speedup vs baseline: 3.3599x; 2.2125x over previous
#include <cuda_runtime.h>
#include <math.h>

#define NN    100000
#define EE    1600000
#define HH    4
#define DD    128
#define BM    64
#define BK    16

// ---------------- scratch (device globals) ----------------
__device__ float g_h[NN * DD];       // x @ W
__device__ float g_skip[NN * DD];    // x @ skip_W
__device__ float g_Wh[128 * 256];    // tf32-hi of [W | skip_W]
__device__ float g_Wl[128 * 256];    // tf32-lo
__device__ float g_as[NN * HH];
__device__ float g_ad[NN * HH];
__device__ int   g_cnt[NN];
__device__ int   g_exc[NN];
__device__ int   g_bsum[128];
__device__ int   g_boff[128];
__device__ int   g_off[NN + 1];
__device__ int   g_cur[NN];
__device__ int   g_esrc[EE];
__device__ int   g_is64;

// ---------------- helpers ----------------
__device__ __forceinline__ float lrelu(float v) { return v > 0.0f ? v : 0.2f * v; }

__device__ __forceinline__ unsigned tf32_of(float x) {
    unsigned u; asm("cvt.rna.tf32.f32 %0, %1;" : "=r"(u) : "f"(x)); return u;
}

__device__ __forceinline__ void mma_tf32(float4& c, const float a[4], float b0, float b1) {
    asm volatile(
        "mma.sync.aligned.m16n8k8.row.col.f32.tf32.tf32.f32 "
        "{%0,%1,%2,%3}, {%4,%5,%6,%7}, {%8,%9}, {%0,%1,%2,%3};"
        : "+f"(c.x), "+f"(c.y), "+f"(c.z), "+f"(c.w)
        : "r"(__float_as_uint(a[0])), "r"(__float_as_uint(a[1])),
          "r"(__float_as_uint(a[2])), "r"(__float_as_uint(a[3])),
          "r"(__float_as_uint(b0)), "r"(__float_as_uint(b1)));
}

__device__ __forceinline__ int load_dst(const void* ei, int i) {
    return g_is64 ? (int)((const long long*)ei)[EE + i] : ((const int*)ei)[EE + i];
}
__device__ __forceinline__ void load_edge(const void* ei, int i, int& s, int& d) {
    if (g_is64) {
        const long long* p = (const long long*)ei;
        s = (int)p[i]; d = (int)p[EE + i];
    } else {
        const int* p = (const int*)ei;
        s = p[i]; d = p[EE + i];
    }
}

// ---------------- kernels ----------------
__global__ void detect_k(const long long* ei) {
    if (blockIdx.x == 0 && threadIdx.x == 0) {
        int ok64 = 1;
        for (int i = 0; i < 64; i++) {
            long long v = ei[i];
            if (v < 0 || v >= NN) { ok64 = 0; break; }
        }
        g_is64 = ok64;
    }
}

// split [W | skip_W] into tf32 hi/lo, layout [128 k][256 n]
__global__ void wsplit_k(const float* __restrict__ W, const float* __restrict__ sW) {
    int i = blockIdx.x * blockDim.x + threadIdx.x;
    if (i >= 128 * 256) return;
    int r = i >> 8, c = i & 255;
    float v = (c < 128) ? W[r * 128 + c] : sW[r * 128 + (c - 128)];
    float hi = __uint_as_float(tf32_of(v));
    g_Wh[i] = hi;
    g_Wl[i] = __uint_as_float(tf32_of(v - hi));
}

__global__ void init_k() {
    int i = blockIdx.x * blockDim.x + threadIdx.x;
    if (i < NN) g_cnt[i] = 0;
}

__global__ void hist_k(const void* __restrict__ ei) {
    int i = blockIdx.x * blockDim.x + threadIdx.x;
    if (i >= EE) return;
    atomicAdd(&g_cnt[load_dst(ei, i)], 1);
}

__global__ void __launch_bounds__(1024) scanA_k() {
    __shared__ int sd[1024];
    int t = threadIdx.x;
    int i = blockIdx.x * 1024 + t;
    int v = (i < NN) ? g_cnt[i] : 0;
    sd[t] = v;
    __syncthreads();
#pragma unroll
    for (int o = 1; o < 1024; o <<= 1) {
        int x = (t >= o) ? sd[t - o] : 0;
        __syncthreads();
        sd[t] += x;
        __syncthreads();
    }
    if (i < NN) g_exc[i] = sd[t] - v;
    if (t == 1023) g_bsum[blockIdx.x] = sd[t];
}

__global__ void scanB_k(int nblocks) {
    __shared__ int sd[128];
    int t = threadIdx.x;
    int v = (t < nblocks) ? g_bsum[t] : 0;
    sd[t] = v;
    __syncthreads();
#pragma unroll
    for (int o = 1; o < 128; o <<= 1) {
        int x = (t >= o) ? sd[t - o] : 0;
        __syncthreads();
        sd[t] += x;
        __syncthreads();
    }
    g_boff[t] = sd[t] - v;
}

__global__ void scanC_k() {
    int i = blockIdx.x * blockDim.x + threadIdx.x;
    if (i < NN) {
        int off = g_exc[i] + g_boff[i >> 10];
        g_off[i] = off;
        g_cur[i] = off;
    }
    if (i == 0) g_off[NN] = EE;
}

__global__ void scatter_k(const void* __restrict__ ei) {
    int i = blockIdx.x * blockDim.x + threadIdx.x;
    if (i >= EE) return;
    int s, d;
    load_edge(ei, i, s, d);
    int pos = atomicAdd(&g_cur[d], 1);
    g_esrc[pos] = s;
}

// tf32 split GEMM: [N,128] x [128,256] -> g_h | g_skip
// block 256 thr = 8 warps (2m x 4n), tile M=64 N=256, warp tile 32x64
__global__ void __launch_bounds__(256) gemm_tf32_k(const float* __restrict__ x) {
    __shared__ float xs_h[BM * 20], xs_l[BM * 20];
    __shared__ float ws_h[BK * 264], ws_l[BK * 264];
    int t = threadIdx.x;
    int wid = t >> 5, lane = t & 31;
    int gid = lane >> 2, tig = lane & 3;
    int wm = wid >> 2, wn = wid & 3;
    int m0 = blockIdx.x * BM;

    float4 acc[2][8];
#pragma unroll
    for (int mi = 0; mi < 2; mi++)
#pragma unroll
        for (int j = 0; j < 8; j++) acc[mi][j] = make_float4(0.f, 0.f, 0.f, 0.f);

    for (int kk = 0; kk < 128; kk += BK) {
        __syncthreads();
        // stage x tile [64 x 16], split hi/lo
        {
            int row = t >> 2, c4 = (t & 3) * 4;
            float4 v = make_float4(0.f, 0.f, 0.f, 0.f);
            if (m0 + row < NN) v = *(const float4*)(x + (size_t)(m0 + row) * 128 + kk + c4);
            float4 hi, lo;
            hi.x = __uint_as_float(tf32_of(v.x)); lo.x = v.x - hi.x;
            hi.y = __uint_as_float(tf32_of(v.y)); lo.y = v.y - hi.y;
            hi.z = __uint_as_float(tf32_of(v.z)); lo.z = v.z - hi.z;
            hi.w = __uint_as_float(tf32_of(v.w)); lo.w = v.w - hi.w;
            *(float4*)&xs_h[row * 20 + c4] = hi;
            *(float4*)&xs_l[row * 20 + c4] = lo;
        }
        // stage w tile [16 x 256] hi/lo
#pragma unroll
        for (int i = 0; i < 4; i++) {
            int fi = i * 256 + t;
            int r = fi >> 6;
            int c = (fi & 63) * 4;
            *(float4*)&ws_h[r * 264 + c] = *(const float4*)&g_Wh[(kk + r) * 256 + c];
            *(float4*)&ws_l[r * 264 + c] = *(const float4*)&g_Wl[(kk + r) * 256 + c];
        }
        __syncthreads();

#pragma unroll
        for (int ks = 0; ks < BK; ks += 8) {
            float ah[2][4], al[2][4];
#pragma unroll
            for (int mi = 0; mi < 2; mi++) {
                int rb = wm * 32 + mi * 16 + gid;
                ah[mi][0] = xs_h[rb * 20 + ks + tig];
                ah[mi][1] = xs_h[(rb + 8) * 20 + ks + tig];
                ah[mi][2] = xs_h[rb * 20 + ks + tig + 4];
                ah[mi][3] = xs_h[(rb + 8) * 20 + ks + tig + 4];
                al[mi][0] = xs_l[rb * 20 + ks + tig];
                al[mi][1] = xs_l[(rb + 8) * 20 + ks + tig];
                al[mi][2] = xs_l[rb * 20 + ks + tig + 4];
                al[mi][3] = xs_l[(rb + 8) * 20 + ks + tig + 4];
            }
#pragma unroll
            for (int j = 0; j < 8; j++) {
                int col = wn * 64 + j * 8 + gid;
                float bh0 = ws_h[(ks + tig) * 264 + col];
                float bh1 = ws_h[(ks + tig + 4) * 264 + col];
                float bl0 = ws_l[(ks + tig) * 264 + col];
                float bl1 = ws_l[(ks + tig + 4) * 264 + col];
#pragma unroll
                for (int mi = 0; mi < 2; mi++) {
                    mma_tf32(acc[mi][j], ah[mi], bh0, bh1);
                    mma_tf32(acc[mi][j], al[mi], bh0, bh1);
                    mma_tf32(acc[mi][j], ah[mi], bl0, bl1);
                }
            }
        }
    }

    // epilogue
#pragma unroll
    for (int mi = 0; mi < 2; mi++) {
#pragma unroll
        for (int j = 0; j < 8; j++) {
            int col = wn * 64 + j * 8 + tig * 2;
            int row = m0 + wm * 32 + mi * 16 + gid;
            float* b0 = (col < 128) ? (g_h + (size_t)row * 128 + col)
                                    : (g_skip + (size_t)row * 128 + (col - 128));
            if (row < NN) *(float2*)b0 = make_float2(acc[mi][j].x, acc[mi][j].y);
            int row2 = row + 8;
            float* b1 = (col < 128) ? (g_h + (size_t)row2 * 128 + col)
                                    : (g_skip + (size_t)row2 * 128 + (col - 128));
            if (row2 < NN) *(float2*)b1 = make_float2(acc[mi][j].z, acc[mi][j].w);
        }
    }
}

// warp per node: per-head logits
__global__ void att_k(const float* __restrict__ asrc, const float* __restrict__ adst) {
    int g = blockIdx.x * blockDim.x + threadIdx.x;
    int n = g >> 5, lane = g & 31;
    if (n >= NN) return;
    float4 hv = ((const float4*)(g_h + (size_t)n * 128))[lane];
    float4 vs = ((const float4*)asrc)[lane];
    float4 vd = ((const float4*)adst)[lane];
    float ps = hv.x * vs.x + hv.y * vs.y + hv.z * vs.z + hv.w * vs.w;
    float pd = hv.x * vd.x + hv.y * vd.y + hv.z * vd.z + hv.w * vd.w;
#pragma unroll
    for (int o = 4; o >= 1; o >>= 1) {
        ps += __shfl_down_sync(0xffffffff, ps, o);
        pd += __shfl_down_sync(0xffffffff, pd, o);
    }
    if ((lane & 7) == 0) {
        int h = lane >> 3;
        g_as[n * 4 + h] = ps;
        g_ad[n * 4 + h] = pd;
    }
}

// Fused CSR aggregation + softmax-norm + bias + skip + LayerNorm (warp/node)
__global__ void __launch_bounds__(256) eagg_k(const float* __restrict__ gb,
                                              const float* __restrict__ sb,
                                              const float* __restrict__ lg,
                                              const float* __restrict__ lb,
                                              float* __restrict__ out) {
    int g = blockIdx.x * blockDim.x + threadIdx.x;
    int n = g >> 5, lane = g & 31;
    if (n >= NN) return;
    int h = lane >> 3;

    float ad_h = g_ad[n * 4 + h];

    // self loop
    float p = __expf(lrelu(g_as[n * 4 + h] + ad_h));
    float4 hv = ((const float4*)(g_h + (size_t)n * 128))[lane];
    float z = p;
    float4 acc = make_float4(p * hv.x, p * hv.y, p * hv.z, p * hv.w);

    int e   = g_off[n];
    int end = g_off[n + 1];
    for (; e + 4 <= end; e += 4) {
        int s0 = g_esrc[e], s1 = g_esrc[e + 1], s2 = g_esrc[e + 2], s3 = g_esrc[e + 3];
        float a0 = __ldg(g_as + s0 * 4 + h);
        float a1 = __ldg(g_as + s1 * 4 + h);
        float a2 = __ldg(g_as + s2 * 4 + h);
        float a3 = __ldg(g_as + s3 * 4 + h);
        float4 h0 = ((const float4*)(g_h + (size_t)s0 * 128))[lane];
        float4 h1 = ((const float4*)(g_h + (size_t)s1 * 128))[lane];
        float4 h2 = ((const float4*)(g_h + (size_t)s2 * 128))[lane];
        float4 h3 = ((const float4*)(g_h + (size_t)s3 * 128))[lane];
        float p0 = __expf(lrelu(a0 + ad_h));
        float p1 = __expf(lrelu(a1 + ad_h));
        float p2 = __expf(lrelu(a2 + ad_h));
        float p3 = __expf(lrelu(a3 + ad_h));
        z += (p0 + p1) + (p2 + p3);
        acc.x += p0 * h0.x + p1 * h1.x + p2 * h2.x + p3 * h3.x;
        acc.y += p0 * h0.y + p1 * h1.y + p2 * h2.y + p3 * h3.y;
        acc.z += p0 * h0.z + p1 * h1.z + p2 * h2.z + p3 * h3.z;
        acc.w += p0 * h0.w + p1 * h1.w + p2 * h2.w + p3 * h3.w;
    }
    for (; e < end; e++) {
        int s0 = g_esrc[e];
        float a0 = __ldg(g_as + s0 * 4 + h);
        float4 h0 = ((const float4*)(g_h + (size_t)s0 * 128))[lane];
        float p0 = __expf(lrelu(a0 + ad_h));
        z += p0;
        acc.x += p0 * h0.x; acc.y += p0 * h0.y;
        acc.z += p0 * h0.z; acc.w += p0 * h0.w;
    }

    float inv = 1.0f / (z + 1e-16f);
    float4 sk = ((const float4*)(g_skip + (size_t)n * 128))[lane];
    float4 b1 = ((const float4*)gb)[lane];
    float4 b2 = ((const float4*)sb)[lane];
    float4 v;
    v.x = acc.x * inv + sk.x + b1.x + b2.x;
    v.y = acc.y * inv + sk.y + b1.y + b2.y;
    v.z = acc.z * inv + sk.z + b1.z + b2.z;
    v.w = acc.w * inv + sk.w + b1.w + b2.w;

    float sum = v.x + v.y + v.z + v.w;
    float sq  = v.x * v.x + v.y * v.y + v.z * v.z + v.w * v.w;
#pragma unroll
    for (int o = 16; o >= 1; o >>= 1) {
        sum += __shfl_xor_sync(0xffffffff, sum, o);
        sq  += __shfl_xor_sync(0xffffffff, sq, o);
    }
    float mu  = sum * (1.0f / 128.0f);
    float var = sq * (1.0f / 128.0f) - mu * mu;
    float invs = rsqrtf(var + 1e-5f);
    float4 gg = ((const float4*)lg)[lane];
    float4 bb = ((const float4*)lb)[lane];
    float4 o4;
    o4.x = (v.x - mu) * invs * gg.x + bb.x;
    o4.y = (v.y - mu) * invs * gg.y + bb.y;
    o4.z = (v.z - mu) * invs * gg.z + bb.z;
    o4.w = (v.w - mu) * invs * gg.w + bb.w;
    ((float4*)(out + (size_t)n * 128))[lane] = o4;
}

// ---------------- launch ----------------
extern "C" void kernel_launch(void* const* d_in, const int* in_sizes, int n_in,
                              void* d_out, int out_size) {
    const float* x        = (const float*)d_in[0];
    const void*  ei       = d_in[1];
    const float* W        = (const float*)d_in[2];
    const float* att_src  = (const float*)d_in[3];
    const float* att_dst  = (const float*)d_in[4];
    const float* gat_bias = (const float*)d_in[5];
    const float* skip_W   = (const float*)d_in[6];
    const float* skip_b   = (const float*)d_in[7];
    const float* ln_g     = (const float*)d_in[8];
    const float* ln_b     = (const float*)d_in[9];
    float* out = (float*)d_out;

    int nblocks = (NN + 1023) / 1024;

    detect_k<<<1, 32>>>((const long long*)ei);                 // 0
    wsplit_k<<<128, 256>>>(W, skip_W);                         // 1
    init_k<<<(NN + 255) / 256, 256>>>();                       // 2
    gemm_tf32_k<<<(NN + BM - 1) / BM, 256>>>(x);               // 3 <- ncu slot
    att_k<<<(NN * 32 + 255) / 256, 256>>>(att_src, att_dst);   // 4
    hist_k<<<(EE + 255) / 256, 256>>>(ei);                     // 5
    scanA_k<<<nblocks, 1024>>>();                              // 6
    scanB_k<<<1, 128>>>(nblocks);                              // 7
    scanC_k<<<(NN + 255) / 256, 256>>>();                      // 8
    scatter_k<<<(EE + 255) / 256, 256>>>(ei);                  // 9
    eagg_k<<<(NN * 32 + 255) / 256, 256>>>(gat_bias, skip_b, ln_g, ln_b, out);  // 10
}

// round 5
// speedup vs baseline: 4.2279x; 1.2583x over previous
#include <cuda_runtime.h>
#include <cuda_bf16.h>
#include <math.h>

#define NN    100000
#define EE    1600000
#define HH    4
#define DD    128
#define BM    64
#define BK    16

// ---------------- scratch (device globals) ----------------
__device__ unsigned g_hb[NN * 64];     // h as packed bf16x2 [N][64]
__device__ float    g_skip[NN * DD];   // x @ skip_W (fp32)
__device__ unsigned g_Wbh[64 * 256];   // W|skip_W bf16-hi, packed k-pairs [64][256]
__device__ unsigned g_Wbl[64 * 256];   // bf16-lo
__device__ float    g_as[NN * HH];
__device__ float    g_ad[NN * HH];
__device__ int      g_cnt[NN];
__device__ int      g_exc[NN];
__device__ int      g_bsum[128];
__device__ int      g_boff[128];
__device__ int      g_off[NN + 1];
__device__ int      g_cur[NN];
__device__ int      g_esrc[EE];
__device__ int      g_is64;

// ---------------- helpers ----------------
__device__ __forceinline__ float lrelu(float v) { return v > 0.0f ? v : 0.2f * v; }

__device__ __forceinline__ void mma_bf16(float4& c, const unsigned a[4],
                                         unsigned b0, unsigned b1) {
    asm volatile(
        "mma.sync.aligned.m16n8k16.row.col.f32.bf16.bf16.f32 "
        "{%0,%1,%2,%3}, {%4,%5,%6,%7}, {%8,%9}, {%0,%1,%2,%3};"
        : "+f"(c.x), "+f"(c.y), "+f"(c.z), "+f"(c.w)
        : "r"(a[0]), "r"(a[1]), "r"(a[2]), "r"(a[3]), "r"(b0), "r"(b1));
}

__device__ __forceinline__ unsigned pack_hi(float a, float b) {
    __nv_bfloat162 r = __floats2bfloat162_rn(a, b);
    return *(unsigned*)&r;
}

__device__ __forceinline__ int load_dst(const void* ei, int i) {
    return g_is64 ? (int)((const long long*)ei)[EE + i] : ((const int*)ei)[EE + i];
}
__device__ __forceinline__ void load_edge(const void* ei, int i, int& s, int& d) {
    if (g_is64) {
        const long long* p = (const long long*)ei;
        s = (int)p[i]; d = (int)p[EE + i];
    } else {
        const int* p = (const int*)ei;
        s = p[i]; d = p[EE + i];
    }
}

// unpack 4 bf16 (uint2) -> 4 floats
__device__ __forceinline__ float4 unpack4(uint2 w) {
    float2 f0 = __bfloat1622float2(*(__nv_bfloat162*)&w.x);
    float2 f1 = __bfloat1622float2(*(__nv_bfloat162*)&w.y);
    return make_float4(f0.x, f0.y, f1.x, f1.y);
}

// ---------------- kernels ----------------
__global__ void detect_k(const long long* ei) {
    if (blockIdx.x == 0 && threadIdx.x == 0) {
        int ok64 = 1;
        for (int i = 0; i < 64; i++) {
            long long v = ei[i];
            if (v < 0 || v >= NN) { ok64 = 0; break; }
        }
        g_is64 = ok64;
    }
}

// split [W | skip_W] -> bf16 hi/lo, packed k-pairs: [64 kp][256 n]
__global__ void wsplit_k(const float* __restrict__ W, const float* __restrict__ sW) {
    int i = blockIdx.x * blockDim.x + threadIdx.x;
    if (i >= 64 * 256) return;
    int kp = i >> 8, c = i & 255;
    float v0, v1;
    if (c < 128) { v0 = W[(2 * kp) * 128 + c];       v1 = W[(2 * kp + 1) * 128 + c]; }
    else         { v0 = sW[(2 * kp) * 128 + c - 128]; v1 = sW[(2 * kp + 1) * 128 + c - 128]; }
    float h0 = __bfloat162float(__float2bfloat16_rn(v0));
    float h1 = __bfloat162float(__float2bfloat16_rn(v1));
    g_Wbh[i] = pack_hi(v0, v1);
    g_Wbl[i] = pack_hi(v0 - h0, v1 - h1);
}

__global__ void init_k() {
    int i = blockIdx.x * blockDim.x + threadIdx.x;
    if (i < NN) g_cnt[i] = 0;
}

__global__ void hist_k(const void* __restrict__ ei) {
    int i = blockIdx.x * blockDim.x + threadIdx.x;
    if (i >= EE) return;
    atomicAdd(&g_cnt[load_dst(ei, i)], 1);
}

__global__ void __launch_bounds__(1024) scanA_k() {
    __shared__ int sd[1024];
    int t = threadIdx.x;
    int i = blockIdx.x * 1024 + t;
    int v = (i < NN) ? g_cnt[i] : 0;
    sd[t] = v;
    __syncthreads();
#pragma unroll
    for (int o = 1; o < 1024; o <<= 1) {
        int x = (t >= o) ? sd[t - o] : 0;
        __syncthreads();
        sd[t] += x;
        __syncthreads();
    }
    if (i < NN) g_exc[i] = sd[t] - v;
    if (t == 1023) g_bsum[blockIdx.x] = sd[t];
}

__global__ void scanB_k(int nblocks) {
    __shared__ int sd[128];
    int t = threadIdx.x;
    int v = (t < nblocks) ? g_bsum[t] : 0;
    sd[t] = v;
    __syncthreads();
#pragma unroll
    for (int o = 1; o < 128; o <<= 1) {
        int x = (t >= o) ? sd[t - o] : 0;
        __syncthreads();
        sd[t] += x;
        __syncthreads();
    }
    g_boff[t] = sd[t] - v;
}

__global__ void scanC_k() {
    int i = blockIdx.x * blockDim.x + threadIdx.x;
    if (i < NN) {
        int off = g_exc[i] + g_boff[i >> 10];
        g_off[i] = off;
        g_cur[i] = off;
    }
    if (i == 0) g_off[NN] = EE;
}

__global__ void scatter_k(const void* __restrict__ ei) {
    int i = blockIdx.x * blockDim.x + threadIdx.x;
    if (i >= EE) return;
    int s, d;
    load_edge(ei, i, s, d);
    int pos = atomicAdd(&g_cur[d], 1);
    g_esrc[pos] = s;
}

// bf16 split GEMM: [N,128] x [128,256] -> g_hb (bf16, cols 0..127) | g_skip (fp32)
// block 256 thr = 8 warps (2m x 4n), tile M=64 N=256 K=16/iter, warp tile 32x64
#define XP 12    // A smem pitch in u32 (conflict-free for frag reads)
#define WP 264   // B smem pitch in u32
__global__ void __launch_bounds__(256) gemm_bf16_k(const float* __restrict__ x) {
    __shared__ unsigned xs_h[BM * XP], xs_l[BM * XP];
    __shared__ unsigned ws_h[8 * WP],  ws_l[8 * WP];
    int t = threadIdx.x;
    int wid = t >> 5, lane = t & 31;
    int gid = lane >> 2, tig = lane & 3;
    int wm = wid >> 2, wn = wid & 3;
    int m0 = blockIdx.x * BM;

    float4 acc[2][8];
#pragma unroll
    for (int mi = 0; mi < 2; mi++)
#pragma unroll
        for (int j = 0; j < 8; j++) acc[mi][j] = make_float4(0.f, 0.f, 0.f, 0.f);

    for (int kk = 0; kk < 128; kk += BK) {
        __syncthreads();
        // stage x tile [64 x 16], split into bf16 hi/lo, pack k-pairs
        {
            int row = t >> 2;
            int q   = (t & 3);           // quarter: k offsets q*4..q*4+3
            float4 v = make_float4(0.f, 0.f, 0.f, 0.f);
            if (m0 + row < NN)
                v = *(const float4*)(x + (size_t)(m0 + row) * 128 + kk + q * 4);
            float hx = __bfloat162float(__float2bfloat16_rn(v.x));
            float hy = __bfloat162float(__float2bfloat16_rn(v.y));
            float hz = __bfloat162float(__float2bfloat16_rn(v.z));
            float hw = __bfloat162float(__float2bfloat16_rn(v.w));
            int b = row * XP + q * 2;
            xs_h[b]     = pack_hi(v.x, v.y);
            xs_h[b + 1] = pack_hi(v.z, v.w);
            xs_l[b]     = pack_hi(v.x - hx, v.y - hy);
            xs_l[b + 1] = pack_hi(v.z - hz, v.w - hw);
        }
        // stage W tile: kpair rows kk/2 .. kk/2+7, 256 cols (uint4 copies)
        {
            int kp0 = kk >> 1;
#pragma unroll
            for (int i = 0; i < 2; i++) {
                int fi = i * 256 + t;          // uint4 index, 512 total
                int r  = fi >> 6;              // 0..7
                int c4 = (fi & 63) * 4;
                *(uint4*)&ws_h[r * WP + c4] = *(const uint4*)&g_Wbh[(kp0 + r) * 256 + c4];
                *(uint4*)&ws_l[r * WP + c4] = *(const uint4*)&g_Wbl[(kp0 + r) * 256 + c4];
            }
        }
        __syncthreads();

        unsigned ah[2][4], al[2][4];
#pragma unroll
        for (int mi = 0; mi < 2; mi++) {
            int rb = wm * 32 + mi * 16 + gid;
            ah[mi][0] = xs_h[rb * XP + tig];
            ah[mi][1] = xs_h[(rb + 8) * XP + tig];
            ah[mi][2] = xs_h[rb * XP + tig + 4];
            ah[mi][3] = xs_h[(rb + 8) * XP + tig + 4];
            al[mi][0] = xs_l[rb * XP + tig];
            al[mi][1] = xs_l[(rb + 8) * XP + tig];
            al[mi][2] = xs_l[rb * XP + tig + 4];
            al[mi][3] = xs_l[(rb + 8) * XP + tig + 4];
        }
#pragma unroll
        for (int j = 0; j < 8; j++) {
            int col = wn * 64 + j * 8 + gid;
            unsigned bh0 = ws_h[tig * WP + col];
            unsigned bh1 = ws_h[(tig + 4) * WP + col];
            unsigned bl0 = ws_l[tig * WP + col];
            unsigned bl1 = ws_l[(tig + 4) * WP + col];
#pragma unroll
            for (int mi = 0; mi < 2; mi++) {
                mma_bf16(acc[mi][j], ah[mi], bh0, bh1);
                mma_bf16(acc[mi][j], al[mi], bh0, bh1);
                mma_bf16(acc[mi][j], ah[mi], bl0, bl1);
            }
        }
    }

    // epilogue: cols<128 -> g_hb (bf16x2), cols>=128 -> g_skip (fp32)
#pragma unroll
    for (int mi = 0; mi < 2; mi++) {
#pragma unroll
        for (int j = 0; j < 8; j++) {
            int col  = wn * 64 + j * 8 + tig * 2;
            int row  = m0 + wm * 32 + mi * 16 + gid;
            int row2 = row + 8;
            if (col < 128) {
                int ci = col >> 1;
                if (row  < NN) g_hb[(size_t)row  * 64 + ci] = pack_hi(acc[mi][j].x, acc[mi][j].y);
                if (row2 < NN) g_hb[(size_t)row2 * 64 + ci] = pack_hi(acc[mi][j].z, acc[mi][j].w);
            } else {
                int c = col - 128;
                if (row  < NN) *(float2*)(g_skip + (size_t)row  * 128 + c) =
                    make_float2(acc[mi][j].x, acc[mi][j].y);
                if (row2 < NN) *(float2*)(g_skip + (size_t)row2 * 128 + c) =
                    make_float2(acc[mi][j].z, acc[mi][j].w);
            }
        }
    }
}

// warp per node: per-head logits from bf16 h
__global__ void att_k(const float* __restrict__ asrc, const float* __restrict__ adst) {
    int g = blockIdx.x * blockDim.x + threadIdx.x;
    int n = g >> 5, lane = g & 31;
    if (n >= NN) return;
    float4 hv = unpack4(((const uint2*)(g_hb + (size_t)n * 64))[lane]);
    float4 vs = ((const float4*)asrc)[lane];
    float4 vd = ((const float4*)adst)[lane];
    float ps = hv.x * vs.x + hv.y * vs.y + hv.z * vs.z + hv.w * vs.w;
    float pd = hv.x * vd.x + hv.y * vd.y + hv.z * vd.z + hv.w * vd.w;
#pragma unroll
    for (int o = 4; o >= 1; o >>= 1) {
        ps += __shfl_down_sync(0xffffffff, ps, o);
        pd += __shfl_down_sync(0xffffffff, pd, o);
    }
    if ((lane & 7) == 0) {
        int h = lane >> 3;
        g_as[n * 4 + h] = ps;
        g_ad[n * 4 + h] = pd;
    }
}

// Fused CSR aggregation + softmax-norm + bias + skip + LayerNorm (warp/node)
__global__ void __launch_bounds__(256) eagg_k(const float* __restrict__ gb,
                                              const float* __restrict__ sb,
                                              const float* __restrict__ lg,
                                              const float* __restrict__ lb,
                                              float* __restrict__ out) {
    int g = blockIdx.x * blockDim.x + threadIdx.x;
    int n = g >> 5, lane = g & 31;
    if (n >= NN) return;
    int h = lane >> 3;

    float ad_h = g_ad[n * 4 + h];

    // self loop
    float p = __expf(lrelu(g_as[n * 4 + h] + ad_h));
    float4 hv = unpack4(((const uint2*)(g_hb + (size_t)n * 64))[lane]);
    float z = p;
    float4 acc = make_float4(p * hv.x, p * hv.y, p * hv.z, p * hv.w);

    int e   = g_off[n];
    int end = g_off[n + 1];
    for (; e + 4 <= end; e += 4) {
        int s0 = g_esrc[e], s1 = g_esrc[e + 1], s2 = g_esrc[e + 2], s3 = g_esrc[e + 3];
        float a0 = __ldg(g_as + s0 * 4 + h);
        float a1 = __ldg(g_as + s1 * 4 + h);
        float a2 = __ldg(g_as + s2 * 4 + h);
        float a3 = __ldg(g_as + s3 * 4 + h);
        uint2 w0 = ((const uint2*)(g_hb + (size_t)s0 * 64))[lane];
        uint2 w1 = ((const uint2*)(g_hb + (size_t)s1 * 64))[lane];
        uint2 w2 = ((const uint2*)(g_hb + (size_t)s2 * 64))[lane];
        uint2 w3 = ((const uint2*)(g_hb + (size_t)s3 * 64))[lane];
        float p0 = __expf(lrelu(a0 + ad_h));
        float p1 = __expf(lrelu(a1 + ad_h));
        float p2 = __expf(lrelu(a2 + ad_h));
        float p3 = __expf(lrelu(a3 + ad_h));
        z += (p0 + p1) + (p2 + p3);
        float4 h0 = unpack4(w0), h1 = unpack4(w1), h2 = unpack4(w2), h3 = unpack4(w3);
        acc.x += p0 * h0.x + p1 * h1.x + p2 * h2.x + p3 * h3.x;
        acc.y += p0 * h0.y + p1 * h1.y + p2 * h2.y + p3 * h3.y;
        acc.z += p0 * h0.z + p1 * h1.z + p2 * h2.z + p3 * h3.z;
        acc.w += p0 * h0.w + p1 * h1.w + p2 * h2.w + p3 * h3.w;
    }
    for (; e < end; e++) {
        int s0 = g_esrc[e];
        float a0 = __ldg(g_as + s0 * 4 + h);
        float4 h0 = unpack4(((const uint2*)(g_hb + (size_t)s0 * 64))[lane]);
        float p0 = __expf(lrelu(a0 + ad_h));
        z += p0;
        acc.x += p0 * h0.x; acc.y += p0 * h0.y;
        acc.z += p0 * h0.z; acc.w += p0 * h0.w;
    }

    float inv = 1.0f / (z + 1e-16f);
    float4 sk = ((const float4*)(g_skip + (size_t)n * 128))[lane];
    float4 b1 = ((const float4*)gb)[lane];
    float4 b2 = ((const float4*)sb)[lane];
    float4 v;
    v.x = acc.x * inv + sk.x + b1.x + b2.x;
    v.y = acc.y * inv + sk.y + b1.y + b2.y;
    v.z = acc.z * inv + sk.z + b1.z + b2.z;
    v.w = acc.w * inv + sk.w + b1.w + b2.w;

    float sum = v.x + v.y + v.z + v.w;
    float sq  = v.x * v.x + v.y * v.y + v.z * v.z + v.w * v.w;
#pragma unroll
    for (int o = 16; o >= 1; o >>= 1) {
        sum += __shfl_xor_sync(0xffffffff, sum, o);
        sq  += __shfl_xor_sync(0xffffffff, sq, o);
    }
    float mu  = sum * (1.0f / 128.0f);
    float var = sq * (1.0f / 128.0f) - mu * mu;
    float invs = rsqrtf(var + 1e-5f);
    float4 gg = ((const float4*)lg)[lane];
    float4 bb = ((const float4*)lb)[lane];
    float4 o4;
    o4.x = (v.x - mu) * invs * gg.x + bb.x;
    o4.y = (v.y - mu) * invs * gg.y + bb.y;
    o4.z = (v.z - mu) * invs * gg.z + bb.z;
    o4.w = (v.w - mu) * invs * gg.w + bb.w;
    ((float4*)(out + (size_t)n * 128))[lane] = o4;
}

// ---------------- launch ----------------
extern "C" void kernel_launch(void* const* d_in, const int* in_sizes, int n_in,
                              void* d_out, int out_size) {
    const float* x        = (const float*)d_in[0];
    const void*  ei       = d_in[1];
    const float* W        = (const float*)d_in[2];
    const float* att_src  = (const float*)d_in[3];
    const float* att_dst  = (const float*)d_in[4];
    const float* gat_bias = (const float*)d_in[5];
    const float* skip_W   = (const float*)d_in[6];
    const float* skip_b   = (const float*)d_in[7];
    const float* ln_g     = (const float*)d_in[8];
    const float* ln_b     = (const float*)d_in[9];
    float* out = (float*)d_out;

    int nblocks = (NN + 1023) / 1024;

    detect_k<<<1, 32>>>((const long long*)ei);                 // 0
    wsplit_k<<<64, 256>>>(W, skip_W);                          // 1
    init_k<<<(NN + 255) / 256, 256>>>();                       // 2
    gemm_bf16_k<<<(NN + BM - 1) / BM, 256>>>(x);               // 3 <- ncu slot
    att_k<<<(NN * 32 + 255) / 256, 256>>>(att_src, att_dst);   // 4
    hist_k<<<(EE + 255) / 256, 256>>>(ei);                     // 5
    scanA_k<<<nblocks, 1024>>>();                              // 6
    scanB_k<<<1, 128>>>(nblocks);                              // 7
    scanC_k<<<(NN + 255) / 256, 256>>>();                      // 8
    scatter_k<<<(EE + 255) / 256, 256>>>(ei);                  // 9
    eagg_k<<<(NN * 32 + 255) / 256, 256>>>(gat_bias, skip_b, ln_g, ln_b, out);  // 10
}

// round 7
// speedup vs baseline: 4.4968x; 1.0636x over previous
#include <cuda_runtime.h>
#include <cuda_bf16.h>
#include <cuda_fp16.h>
#include <math.h>

#define NN    100000
#define EE    1600000
#define HH    4
#define DD    128
#define BM    64
#define BK    16

// ---------------- scratch (device globals) ----------------
__device__ unsigned g_hf[NN * 64];     // h as packed fp16x2 [N][64]
__device__ float    g_skip[NN * DD];   // x @ skip_W (fp32)
__device__ unsigned g_Wbh[64 * 256];   // W|skip_W bf16-hi, packed k-pairs [64][256]
__device__ unsigned g_Wbl[64 * 256];   // bf16-lo
__device__ float    g_as[NN * HH];
__device__ float    g_ad[NN * HH];
__device__ int      g_cnt[NN];
__device__ int      g_exc[NN];
__device__ int      g_bsum[128];
__device__ int      g_boff[128];
__device__ int      g_off[NN + 1];
__device__ int      g_cur[NN];
__device__ int      g_esrc[EE];
__device__ int      g_is64;

// ---------------- helpers ----------------
__device__ __forceinline__ float lrelu(float v) { return v > 0.0f ? v : 0.2f * v; }

__device__ __forceinline__ void mma_bf16(float4& c, const unsigned a[4],
                                         unsigned b0, unsigned b1) {
    asm volatile(
        "mma.sync.aligned.m16n8k16.row.col.f32.bf16.bf16.f32 "
        "{%0,%1,%2,%3}, {%4,%5,%6,%7}, {%8,%9}, {%0,%1,%2,%3};"
        : "+f"(c.x), "+f"(c.y), "+f"(c.z), "+f"(c.w)
        : "r"(a[0]), "r"(a[1]), "r"(a[2]), "r"(a[3]), "r"(b0), "r"(b1));
}

__device__ __forceinline__ unsigned pack_bf2(float a, float b) {
    __nv_bfloat162 r = __floats2bfloat162_rn(a, b);
    return *(unsigned*)&r;
}
__device__ __forceinline__ unsigned pack_h2(float a, float b) {
    __half2 r = __floats2half2_rn(a, b);
    return *(unsigned*)&r;
}

__device__ __forceinline__ void cp16(unsigned* dst_smem, const unsigned* src) {
    unsigned d = (unsigned)__cvta_generic_to_shared(dst_smem);
    asm volatile("cp.async.cg.shared.global [%0], [%1], 16;" :: "r"(d), "l"(src));
}

__device__ __forceinline__ int load_dst(const void* ei, int i) {
    return g_is64 ? (int)((const long long*)ei)[EE + i] : ((const int*)ei)[EE + i];
}
__device__ __forceinline__ void load_edge(const void* ei, int i, int& s, int& d) {
    if (g_is64) {
        const long long* p = (const long long*)ei;
        s = (int)p[i]; d = (int)p[EE + i];
    } else {
        const int* p = (const int*)ei;
        s = p[i]; d = p[EE + i];
    }
}

// unpack 4 fp16 (uint2) -> 4 floats
__device__ __forceinline__ float4 unpack4(uint2 w) {
    float2 f0 = __half22float2(*(__half2*)&w.x);
    float2 f1 = __half22float2(*(__half2*)&w.y);
    return make_float4(f0.x, f0.y, f1.x, f1.y);
}

// ---------------- kernels ----------------
__global__ void detect_k(const long long* ei) {
    if (blockIdx.x == 0 && threadIdx.x == 0) {
        int ok64 = 1;
        for (int i = 0; i < 64; i++) {
            long long v = ei[i];
            if (v < 0 || v >= NN) { ok64 = 0; break; }
        }
        g_is64 = ok64;
    }
}

// split [W | skip_W] -> bf16 hi/lo, packed k-pairs: [64 kp][256 n]
__global__ void wsplit_k(const float* __restrict__ W, const float* __restrict__ sW) {
    int i = blockIdx.x * blockDim.x + threadIdx.x;
    if (i >= 64 * 256) return;
    int kp = i >> 8, c = i & 255;
    float v0, v1;
    if (c < 128) { v0 = W[(2 * kp) * 128 + c];        v1 = W[(2 * kp + 1) * 128 + c]; }
    else         { v0 = sW[(2 * kp) * 128 + c - 128]; v1 = sW[(2 * kp + 1) * 128 + c - 128]; }
    float h0 = __bfloat162float(__float2bfloat16_rn(v0));
    float h1 = __bfloat162float(__float2bfloat16_rn(v1));
    g_Wbh[i] = pack_bf2(v0, v1);
    g_Wbl[i] = pack_bf2(v0 - h0, v1 - h1);
}

__global__ void init_k() {
    int i = blockIdx.x * blockDim.x + threadIdx.x;
    if (i < NN) g_cnt[i] = 0;
}

__global__ void hist_k(const void* __restrict__ ei) {
    int i = blockIdx.x * blockDim.x + threadIdx.x;
    if (i >= EE) return;
    atomicAdd(&g_cnt[load_dst(ei, i)], 1);
}

__global__ void __launch_bounds__(1024) scanA_k() {
    __shared__ int sd[1024];
    int t = threadIdx.x;
    int i = blockIdx.x * 1024 + t;
    int v = (i < NN) ? g_cnt[i] : 0;
    sd[t] = v;
    __syncthreads();
#pragma unroll
    for (int o = 1; o < 1024; o <<= 1) {
        int x = (t >= o) ? sd[t - o] : 0;
        __syncthreads();
        sd[t] += x;
        __syncthreads();
    }
    if (i < NN) g_exc[i] = sd[t] - v;
    if (t == 1023) g_bsum[blockIdx.x] = sd[t];
}

__global__ void scanB_k(int nblocks) {
    __shared__ int sd[128];
    int t = threadIdx.x;
    int v = (t < nblocks) ? g_bsum[t] : 0;
    sd[t] = v;
    __syncthreads();
#pragma unroll
    for (int o = 1; o < 128; o <<= 1) {
        int x = (t >= o) ? sd[t - o] : 0;
        __syncthreads();
        sd[t] += x;
        __syncthreads();
    }
    g_boff[t] = sd[t] - v;
}

__global__ void scanC_k() {
    int i = blockIdx.x * blockDim.x + threadIdx.x;
    if (i < NN) {
        int off = g_exc[i] + g_boff[i >> 10];
        g_off[i] = off;
        g_cur[i] = off;
    }
    if (i == 0) g_off[NN] = EE;
}

__global__ void scatter_k(const void* __restrict__ ei) {
    int i = blockIdx.x * blockDim.x + threadIdx.x;
    if (i >= EE) return;
    int s, d;
    load_edge(ei, i, s, d);
    int pos = atomicAdd(&g_cur[d], 1);
    g_esrc[pos] = s;
}

// bf16 split GEMM, double-buffered with cp.async:
// [N,128] x [128,256] -> g_hf (fp16, cols 0..127) | g_skip (fp32)
// block 256 thr = 8 warps (2m x 4n), tile M=64 N=256 K=16/iter
#define XP 12    // A smem pitch in u32
#define WP 264   // B smem pitch in u32
__global__ void __launch_bounds__(256) gemm_bf16_k(const float* __restrict__ x) {
    __shared__ __align__(16) unsigned xs_h[2][BM * XP], xs_l[2][BM * XP];
    __shared__ __align__(16) unsigned ws_h[2][8 * WP],  ws_l[2][8 * WP];
    int t = threadIdx.x;
    int wid = t >> 5, lane = t & 31;
    int gid = lane >> 2, tig = lane & 3;
    int wm = wid >> 2, wn = wid & 3;
    int m0 = blockIdx.x * BM;

    int xrow = t >> 2;          // 0..63
    int xq   = t & 3;           // k-quarter
    int wr0  = t >> 6;          // W uint4 copies: i*256+t -> row, col
    int wc0  = (t & 63) * 4;

    float4 acc[2][8];
#pragma unroll
    for (int mi = 0; mi < 2; mi++)
#pragma unroll
        for (int j = 0; j < 8; j++) acc[mi][j] = make_float4(0.f, 0.f, 0.f, 0.f);

    // ---- prologue: stage tile 0 into buffer 0 ----
    {
#pragma unroll
        for (int i = 0; i < 2; i++) {
            int r = wr0 + i * 4;
            cp16(&ws_h[0][r * WP + wc0], &g_Wbh[r * 256 + wc0]);
            cp16(&ws_l[0][r * WP + wc0], &g_Wbl[r * 256 + wc0]);
        }
        asm volatile("cp.async.commit_group;");
        float4 v = make_float4(0.f, 0.f, 0.f, 0.f);
        if (m0 + xrow < NN)
            v = *(const float4*)(x + (size_t)(m0 + xrow) * 128 + xq * 4);
        float hx = __bfloat162float(__float2bfloat16_rn(v.x));
        float hy = __bfloat162float(__float2bfloat16_rn(v.y));
        float hz = __bfloat162float(__float2bfloat16_rn(v.z));
        float hw = __bfloat162float(__float2bfloat16_rn(v.w));
        int b = xrow * XP + xq * 2;
        xs_h[0][b]     = pack_bf2(v.x, v.y);
        xs_h[0][b + 1] = pack_bf2(v.z, v.w);
        xs_l[0][b]     = pack_bf2(v.x - hx, v.y - hy);
        xs_l[0][b + 1] = pack_bf2(v.z - hz, v.w - hw);
        asm volatile("cp.async.wait_group 0;");
        __syncthreads();
    }

    for (int it = 0; it < 8; it++) {
        int cur = it & 1, nxt = cur ^ 1;
        float4 v;
        bool more = (it < 7);
        if (more) {
            int kp0 = ((it + 1) * BK) >> 1;
#pragma unroll
            for (int i = 0; i < 2; i++) {
                int r = wr0 + i * 4;
                cp16(&ws_h[nxt][r * WP + wc0], &g_Wbh[(kp0 + r) * 256 + wc0]);
                cp16(&ws_l[nxt][r * WP + wc0], &g_Wbl[(kp0 + r) * 256 + wc0]);
            }
            asm volatile("cp.async.commit_group;");
            v = make_float4(0.f, 0.f, 0.f, 0.f);
            if (m0 + xrow < NN)
                v = *(const float4*)(x + (size_t)(m0 + xrow) * 128 + (it + 1) * BK + xq * 4);
        }

        // ---- compute on cur ----
        unsigned ah[2][4], al[2][4];
#pragma unroll
        for (int mi = 0; mi < 2; mi++) {
            int rb = wm * 32 + mi * 16 + gid;
            ah[mi][0] = xs_h[cur][rb * XP + tig];
            ah[mi][1] = xs_h[cur][(rb + 8) * XP + tig];
            ah[mi][2] = xs_h[cur][rb * XP + tig + 4];
            ah[mi][3] = xs_h[cur][(rb + 8) * XP + tig + 4];
            al[mi][0] = xs_l[cur][rb * XP + tig];
            al[mi][1] = xs_l[cur][(rb + 8) * XP + tig];
            al[mi][2] = xs_l[cur][rb * XP + tig + 4];
            al[mi][3] = xs_l[cur][(rb + 8) * XP + tig + 4];
        }
#pragma unroll
        for (int j = 0; j < 8; j++) {
            int col = wn * 64 + j * 8 + gid;
            unsigned bh0 = ws_h[cur][tig * WP + col];
            unsigned bh1 = ws_h[cur][(tig + 4) * WP + col];
            unsigned bl0 = ws_l[cur][tig * WP + col];
            unsigned bl1 = ws_l[cur][(tig + 4) * WP + col];
#pragma unroll
            for (int mi = 0; mi < 2; mi++) {
                mma_bf16(acc[mi][j], ah[mi], bh0, bh1);
                mma_bf16(acc[mi][j], al[mi], bh0, bh1);
                mma_bf16(acc[mi][j], ah[mi], bl0, bl1);
            }
        }

        if (more) {
            float hx = __bfloat162float(__float2bfloat16_rn(v.x));
            float hy = __bfloat162float(__float2bfloat16_rn(v.y));
            float hz = __bfloat162float(__float2bfloat16_rn(v.z));
            float hw = __bfloat162float(__float2bfloat16_rn(v.w));
            int b = xrow * XP + xq * 2;
            xs_h[nxt][b]     = pack_bf2(v.x, v.y);
            xs_h[nxt][b + 1] = pack_bf2(v.z, v.w);
            xs_l[nxt][b]     = pack_bf2(v.x - hx, v.y - hy);
            xs_l[nxt][b + 1] = pack_bf2(v.z - hz, v.w - hw);
            asm volatile("cp.async.wait_group 0;");
            __syncthreads();
        }
    }

    // epilogue: cols<128 -> g_hf (fp16x2), cols>=128 -> g_skip (fp32)
#pragma unroll
    for (int mi = 0; mi < 2; mi++) {
#pragma unroll
        for (int j = 0; j < 8; j++) {
            int col  = wn * 64 + j * 8 + tig * 2;
            int row  = m0 + wm * 32 + mi * 16 + gid;
            int row2 = row + 8;
            if (col < 128) {
                int ci = col >> 1;
                if (row  < NN) g_hf[(size_t)row  * 64 + ci] = pack_h2(acc[mi][j].x, acc[mi][j].y);
                if (row2 < NN) g_hf[(size_t)row2 * 64 + ci] = pack_h2(acc[mi][j].z, acc[mi][j].w);
            } else {
                int c = col - 128;
                if (row  < NN) *(float2*)(g_skip + (size_t)row  * 128 + c) =
                    make_float2(acc[mi][j].x, acc[mi][j].y);
                if (row2 < NN) *(float2*)(g_skip + (size_t)row2 * 128 + c) =
                    make_float2(acc[mi][j].z, acc[mi][j].w);
            }
        }
    }
}

// warp per node: per-head logits from fp16 h
__global__ void att_k(const float* __restrict__ asrc, const float* __restrict__ adst) {
    int g = blockIdx.x * blockDim.x + threadIdx.x;
    int n = g >> 5, lane = g & 31;
    if (n >= NN) return;
    float4 hv = unpack4(((const uint2*)(g_hf + (size_t)n * 64))[lane]);
    float4 vs = ((const float4*)asrc)[lane];
    float4 vd = ((const float4*)adst)[lane];
    float ps = hv.x * vs.x + hv.y * vs.y + hv.z * vs.z + hv.w * vs.w;
    float pd = hv.x * vd.x + hv.y * vd.y + hv.z * vd.z + hv.w * vd.w;
#pragma unroll
    for (int o = 4; o >= 1; o >>= 1) {
        ps += __shfl_down_sync(0xffffffff, ps, o);
        pd += __shfl_down_sync(0xffffffff, pd, o);
    }
    if ((lane & 7) == 0) {
        int h = lane >> 3;
        g_as[n * 4 + h] = ps;
        g_ad[n * 4 + h] = pd;
    }
}

// Fused CSR aggregation + softmax-norm + bias + skip + LayerNorm (warp/node)
__global__ void __launch_bounds__(256) eagg_k(const float* __restrict__ gb,
                                              const float* __restrict__ sb,
                                              const float* __restrict__ lg,
                                              const float* __restrict__ lb,
                                              float* __restrict__ out) {
    int g = blockIdx.x * blockDim.x + threadIdx.x;
    int n = g >> 5, lane = g & 31;
    if (n >= NN) return;
    int h = lane >> 3;

    float ad_h = g_ad[n * 4 + h];

    // self loop
    float p = __expf(lrelu(g_as[n * 4 + h] + ad_h));
    float4 hv = unpack4(((const uint2*)(g_hf + (size_t)n * 64))[lane]);
    float z = p;
    float4 acc = make_float4(p * hv.x, p * hv.y, p * hv.z, p * hv.w);

    int e   = g_off[n];
    int end = g_off[n + 1];
    for (; e + 4 <= end; e += 4) {
        int s0 = g_esrc[e], s1 = g_esrc[e + 1], s2 = g_esrc[e + 2], s3 = g_esrc[e + 3];
        float a0 = __ldg(g_as + s0 * 4 + h);
        float a1 = __ldg(g_as + s1 * 4 + h);
        float a2 = __ldg(g_as + s2 * 4 + h);
        float a3 = __ldg(g_as + s3 * 4 + h);
        uint2 w0 = ((const uint2*)(g_hf + (size_t)s0 * 64))[lane];
        uint2 w1 = ((const uint2*)(g_hf + (size_t)s1 * 64))[lane];
        uint2 w2 = ((const uint2*)(g_hf + (size_t)s2 * 64))[lane];
        uint2 w3 = ((const uint2*)(g_hf + (size_t)s3 * 64))[lane];
        float p0 = __expf(lrelu(a0 + ad_h));
        float p1 = __expf(lrelu(a1 + ad_h));
        float p2 = __expf(lrelu(a2 + ad_h));
        float p3 = __expf(lrelu(a3 + ad_h));
        z += (p0 + p1) + (p2 + p3);
        float4 h0 = unpack4(w0), h1 = unpack4(w1), h2 = unpack4(w2), h3 = unpack4(w3);
        acc.x += p0 * h0.x + p1 * h1.x + p2 * h2.x + p3 * h3.x;
        acc.y += p0 * h0.y + p1 * h1.y + p2 * h2.y + p3 * h3.y;
        acc.z += p0 * h0.z + p1 * h1.z + p2 * h2.z + p3 * h3.z;
        acc.w += p0 * h0.w + p1 * h1.w + p2 * h2.w + p3 * h3.w;
    }
    for (; e < end; e++) {
        int s0 = g_esrc[e];
        float a0 = __ldg(g_as + s0 * 4 + h);
        float4 h0 = unpack4(((const uint2*)(g_hf + (size_t)s0 * 64))[lane]);
        float p0 = __expf(lrelu(a0 + ad_h));
        z += p0;
        acc.x += p0 * h0.x; acc.y += p0 * h0.y;
        acc.z += p0 * h0.z; acc.w += p0 * h0.w;
    }

    float inv = 1.0f / (z + 1e-16f);
    float4 sk = ((const float4*)(g_skip + (size_t)n * 128))[lane];
    float4 b1 = ((const float4*)gb)[lane];
    float4 b2 = ((const float4*)sb)[lane];
    float4 v;
    v.x = acc.x * inv + sk.x + b1.x + b2.x;
    v.y = acc.y * inv + sk.y + b1.y + b2.y;
    v.z = acc.z * inv + sk.z + b1.z + b2.z;
    v.w = acc.w * inv + sk.w + b1.w + b2.w;

    float sum = v.x + v.y + v.z + v.w;
    float sq  = v.x * v.x + v.y * v.y + v.z * v.z + v.w * v.w;
#pragma unroll
    for (int o = 16; o >= 1; o >>= 1) {
        sum += __shfl_xor_sync(0xffffffff, sum, o);
        sq  += __shfl_xor_sync(0xffffffff, sq, o);
    }
    float mu  = sum * (1.0f / 128.0f);
    float var = sq * (1.0f / 128.0f) - mu * mu;
    float invs = rsqrtf(var + 1e-5f);
    float4 gg = ((const float4*)lg)[lane];
    float4 bb = ((const float4*)lb)[lane];
    float4 o4;
    o4.x = (v.x - mu) * invs * gg.x + bb.x;
    o4.y = (v.y - mu) * invs * gg.y + bb.y;
    o4.z = (v.z - mu) * invs * gg.z + bb.z;
    o4.w = (v.w - mu) * invs * gg.w + bb.w;
    ((float4*)(out + (size_t)n * 128))[lane] = o4;
}

// ---------------- launch ----------------
extern "C" void kernel_launch(void* const* d_in, const int* in_sizes, int n_in,
                              void* d_out, int out_size) {
    const float* x        = (const float*)d_in[0];
    const void*  ei       = d_in[1];
    const float* W        = (const float*)d_in[2];
    const float* att_src  = (const float*)d_in[3];
    const float* att_dst  = (const float*)d_in[4];
    const float* gat_bias = (const float*)d_in[5];
    const float* skip_W   = (const float*)d_in[6];
    const float* skip_b   = (const float*)d_in[7];
    const float* ln_g     = (const float*)d_in[8];
    const float* ln_b     = (const float*)d_in[9];
    float* out = (float*)d_out;

    int nblocks = (NN + 1023) / 1024;

    detect_k<<<1, 32>>>((const long long*)ei);                 // 0
    wsplit_k<<<64, 256>>>(W, skip_W);                          // 1
    init_k<<<(NN + 255) / 256, 256>>>();                       // 2
    gemm_bf16_k<<<(NN + BM - 1) / BM, 256>>>(x);               // 3 <- ncu slot
    att_k<<<(NN * 32 + 255) / 256, 256>>>(att_src, att_dst);   // 4
    hist_k<<<(EE + 255) / 256, 256>>>(ei);                     // 5
    scanA_k<<<nblocks, 1024>>>();                              // 6
    scanB_k<<<1, 128>>>(nblocks);                              // 7
    scanC_k<<<(NN + 255) / 256, 256>>>();                      // 8
    scatter_k<<<(EE + 255) / 256, 256>>>(ei);                  // 9
    eagg_k<<<(NN * 32 + 255) / 256, 256>>>(gat_bias, skip_b, ln_g, ln_b, out);  // 10
}

// round 9
// speedup vs baseline: 4.7456x; 1.0553x over previous
#include <cuda_runtime.h>
#include <cuda_bf16.h>
#include <cuda_fp16.h>
#include <math.h>

#define NN    100000
#define EE    1600000
#define HH    4
#define DD    128
#define BM    64
#define BK    16

// ---------------- scratch (device globals) ----------------
__device__ unsigned g_hf[NN * 64];     // h as packed fp16x2 [N][64]
__device__ float    g_skip[NN * DD];   // x @ skip_W (fp32)
__device__ unsigned g_Wbh[64 * 256];   // W|skip_W bf16-hi, packed k-pairs [64][256]
__device__ unsigned g_Wbl[64 * 256];   // bf16-lo
__device__ float    g_as[NN * HH];
__device__ float    g_ad[NN * HH];
__device__ int      g_cnt[NN];
__device__ int      g_exc[NN];
__device__ int      g_bsum[128];
__device__ int      g_boff[128];
__device__ int      g_off[NN + 1];
__device__ int      g_cur[NN];
__device__ int      g_esrc[EE];
__device__ int      g_is64;

// ---------------- helpers ----------------
__device__ __forceinline__ float lrelu(float v) { return v > 0.0f ? v : 0.2f * v; }

__device__ __forceinline__ void mma_bf16(float4& c, const unsigned a[4],
                                         unsigned b0, unsigned b1) {
    asm volatile(
        "mma.sync.aligned.m16n8k16.row.col.f32.bf16.bf16.f32 "
        "{%0,%1,%2,%3}, {%4,%5,%6,%7}, {%8,%9}, {%0,%1,%2,%3};"
        : "+f"(c.x), "+f"(c.y), "+f"(c.z), "+f"(c.w)
        : "r"(a[0]), "r"(a[1]), "r"(a[2]), "r"(a[3]), "r"(b0), "r"(b1));
}

__device__ __forceinline__ unsigned pack_bf2(float a, float b) {
    __nv_bfloat162 r = __floats2bfloat162_rn(a, b);
    return *(unsigned*)&r;
}
__device__ __forceinline__ unsigned pack_h2(float a, float b) {
    __half2 r = __floats2half2_rn(a, b);
    return *(unsigned*)&r;
}

__device__ __forceinline__ void cp16(unsigned* dst_smem, const unsigned* src) {
    unsigned d = (unsigned)__cvta_generic_to_shared(dst_smem);
    asm volatile("cp.async.cg.shared.global [%0], [%1], 16;" :: "r"(d), "l"(src));
}

__device__ __forceinline__ int load_dst(const void* ei, int i) {
    return g_is64 ? (int)((const long long*)ei)[EE + i] : ((const int*)ei)[EE + i];
}
__device__ __forceinline__ void load_edge(const void* ei, int i, int& s, int& d) {
    if (g_is64) {
        const long long* p = (const long long*)ei;
        s = (int)p[i]; d = (int)p[EE + i];
    } else {
        const int* p = (const int*)ei;
        s = p[i]; d = p[EE + i];
    }
}

// unpack 4 fp16 (uint2) -> 4 floats
__device__ __forceinline__ float4 unpack4(uint2 w) {
    float2 f0 = __half22float2(*(__half2*)&w.x);
    float2 f1 = __half22float2(*(__half2*)&w.y);
    return make_float4(f0.x, f0.y, f1.x, f1.y);
}

// ---------------- kernels ----------------
__global__ void detect_k(const long long* ei) {
    if (blockIdx.x == 0 && threadIdx.x == 0) {
        int ok64 = 1;
        for (int i = 0; i < 64; i++) {
            long long v = ei[i];
            if (v < 0 || v >= NN) { ok64 = 0; break; }
        }
        g_is64 = ok64;
    }
}

// split [W | skip_W] -> bf16 hi/lo, packed k-pairs: [64 kp][256 n]
__global__ void wsplit_k(const float* __restrict__ W, const float* __restrict__ sW) {
    int i = blockIdx.x * blockDim.x + threadIdx.x;
    if (i >= 64 * 256) return;
    int kp = i >> 8, c = i & 255;
    float v0, v1;
    if (c < 128) { v0 = W[(2 * kp) * 128 + c];        v1 = W[(2 * kp + 1) * 128 + c]; }
    else         { v0 = sW[(2 * kp) * 128 + c - 128]; v1 = sW[(2 * kp + 1) * 128 + c - 128]; }
    float h0 = __bfloat162float(__float2bfloat16_rn(v0));
    float h1 = __bfloat162float(__float2bfloat16_rn(v1));
    g_Wbh[i] = pack_bf2(v0, v1);
    g_Wbl[i] = pack_bf2(v0 - h0, v1 - h1);
}

__global__ void init_k() {
    int i = blockIdx.x * blockDim.x + threadIdx.x;
    if (i < NN) g_cnt[i] = 0;
}

__global__ void hist_k(const void* __restrict__ ei) {
    int i = blockIdx.x * blockDim.x + threadIdx.x;
    if (i >= EE) return;
    atomicAdd(&g_cnt[load_dst(ei, i)], 1);
}

__global__ void __launch_bounds__(1024) scanA_k() {
    __shared__ int sd[1024];
    int t = threadIdx.x;
    int i = blockIdx.x * 1024 + t;
    int v = (i < NN) ? g_cnt[i] : 0;
    sd[t] = v;
    __syncthreads();
#pragma unroll
    for (int o = 1; o < 1024; o <<= 1) {
        int x = (t >= o) ? sd[t - o] : 0;
        __syncthreads();
        sd[t] += x;
        __syncthreads();
    }
    if (i < NN) g_exc[i] = sd[t] - v;
    if (t == 1023) g_bsum[blockIdx.x] = sd[t];
}

__global__ void scanB_k(int nblocks) {
    __shared__ int sd[128];
    int t = threadIdx.x;
    int v = (t < nblocks) ? g_bsum[t] : 0;
    sd[t] = v;
    __syncthreads();
#pragma unroll
    for (int o = 1; o < 128; o <<= 1) {
        int x = (t >= o) ? sd[t - o] : 0;
        __syncthreads();
        sd[t] += x;
        __syncthreads();
    }
    g_boff[t] = sd[t] - v;
}

__global__ void scanC_k() {
    int i = blockIdx.x * blockDim.x + threadIdx.x;
    if (i < NN) {
        int off = g_exc[i] + g_boff[i >> 10];
        g_off[i] = off;
        g_cur[i] = off;
    }
    if (i == 0) g_off[NN] = EE;
}

__global__ void scatter_k(const void* __restrict__ ei) {
    int i = blockIdx.x * blockDim.x + threadIdx.x;
    if (i >= EE) return;
    int s, d;
    load_edge(ei, i, s, d);
    int pos = atomicAdd(&g_cur[d], 1);
    g_esrc[pos] = s;
}

// bf16 split GEMM, double-buffered with cp.async:
// [N,128] x [128,256] -> g_hf (fp16, cols 0..127) | g_skip (fp32)
// block 256 thr = 8 warps (2m x 4n), tile M=64 N=256 K=16/iter
#define XP 12    // A smem pitch in u32
#define WP 264   // B smem pitch in u32
__global__ void __launch_bounds__(256) gemm_bf16_k(const float* __restrict__ x) {
    __shared__ __align__(16) unsigned xs_h[2][BM * XP], xs_l[2][BM * XP];
    __shared__ __align__(16) unsigned ws_h[2][8 * WP],  ws_l[2][8 * WP];
    int t = threadIdx.x;
    int wid = t >> 5, lane = t & 31;
    int gid = lane >> 2, tig = lane & 3;
    int wm = wid >> 2, wn = wid & 3;
    int m0 = blockIdx.x * BM;

    int xrow = t >> 2;
    int xq   = t & 3;
    int wr0  = t >> 6;
    int wc0  = (t & 63) * 4;

    float4 acc[2][8];
#pragma unroll
    for (int mi = 0; mi < 2; mi++)
#pragma unroll
        for (int j = 0; j < 8; j++) acc[mi][j] = make_float4(0.f, 0.f, 0.f, 0.f);

    // ---- prologue ----
    {
#pragma unroll
        for (int i = 0; i < 2; i++) {
            int r = wr0 + i * 4;
            cp16(&ws_h[0][r * WP + wc0], &g_Wbh[r * 256 + wc0]);
            cp16(&ws_l[0][r * WP + wc0], &g_Wbl[r * 256 + wc0]);
        }
        asm volatile("cp.async.commit_group;");
        float4 v = make_float4(0.f, 0.f, 0.f, 0.f);
        if (m0 + xrow < NN)
            v = *(const float4*)(x + (size_t)(m0 + xrow) * 128 + xq * 4);
        float hx = __bfloat162float(__float2bfloat16_rn(v.x));
        float hy = __bfloat162float(__float2bfloat16_rn(v.y));
        float hz = __bfloat162float(__float2bfloat16_rn(v.z));
        float hw = __bfloat162float(__float2bfloat16_rn(v.w));
        int b = xrow * XP + xq * 2;
        xs_h[0][b]     = pack_bf2(v.x, v.y);
        xs_h[0][b + 1] = pack_bf2(v.z, v.w);
        xs_l[0][b]     = pack_bf2(v.x - hx, v.y - hy);
        xs_l[0][b + 1] = pack_bf2(v.z - hz, v.w - hw);
        asm volatile("cp.async.wait_group 0;");
        __syncthreads();
    }

    for (int it = 0; it < 8; it++) {
        int cur = it & 1, nxt = cur ^ 1;
        float4 v;
        bool more = (it < 7);
        if (more) {
            int kp0 = ((it + 1) * BK) >> 1;
#pragma unroll
            for (int i = 0; i < 2; i++) {
                int r = wr0 + i * 4;
                cp16(&ws_h[nxt][r * WP + wc0], &g_Wbh[(kp0 + r) * 256 + wc0]);
                cp16(&ws_l[nxt][r * WP + wc0], &g_Wbl[(kp0 + r) * 256 + wc0]);
            }
            asm volatile("cp.async.commit_group;");
            v = make_float4(0.f, 0.f, 0.f, 0.f);
            if (m0 + xrow < NN)
                v = *(const float4*)(x + (size_t)(m0 + xrow) * 128 + (it + 1) * BK + xq * 4);
        }

        unsigned ah[2][4], al[2][4];
#pragma unroll
        for (int mi = 0; mi < 2; mi++) {
            int rb = wm * 32 + mi * 16 + gid;
            ah[mi][0] = xs_h[cur][rb * XP + tig];
            ah[mi][1] = xs_h[cur][(rb + 8) * XP + tig];
            ah[mi][2] = xs_h[cur][rb * XP + tig + 4];
            ah[mi][3] = xs_h[cur][(rb + 8) * XP + tig + 4];
            al[mi][0] = xs_l[cur][rb * XP + tig];
            al[mi][1] = xs_l[cur][(rb + 8) * XP + tig];
            al[mi][2] = xs_l[cur][rb * XP + tig + 4];
            al[mi][3] = xs_l[cur][(rb + 8) * XP + tig + 4];
        }
#pragma unroll
        for (int j = 0; j < 8; j++) {
            int col = wn * 64 + j * 8 + gid;
            unsigned bh0 = ws_h[cur][tig * WP + col];
            unsigned bh1 = ws_h[cur][(tig + 4) * WP + col];
            unsigned bl0 = ws_l[cur][tig * WP + col];
            unsigned bl1 = ws_l[cur][(tig + 4) * WP + col];
#pragma unroll
            for (int mi = 0; mi < 2; mi++) {
                mma_bf16(acc[mi][j], ah[mi], bh0, bh1);
                mma_bf16(acc[mi][j], al[mi], bh0, bh1);
                mma_bf16(acc[mi][j], ah[mi], bl0, bl1);
            }
        }

        if (more) {
            float hx = __bfloat162float(__float2bfloat16_rn(v.x));
            float hy = __bfloat162float(__float2bfloat16_rn(v.y));
            float hz = __bfloat162float(__float2bfloat16_rn(v.z));
            float hw = __bfloat162float(__float2bfloat16_rn(v.w));
            int b = xrow * XP + xq * 2;
            xs_h[nxt][b]     = pack_bf2(v.x, v.y);
            xs_h[nxt][b + 1] = pack_bf2(v.z, v.w);
            xs_l[nxt][b]     = pack_bf2(v.x - hx, v.y - hy);
            xs_l[nxt][b + 1] = pack_bf2(v.z - hz, v.w - hw);
            asm volatile("cp.async.wait_group 0;");
            __syncthreads();
        }
    }

    // epilogue
#pragma unroll
    for (int mi = 0; mi < 2; mi++) {
#pragma unroll
        for (int j = 0; j < 8; j++) {
            int col  = wn * 64 + j * 8 + tig * 2;
            int row  = m0 + wm * 32 + mi * 16 + gid;
            int row2 = row + 8;
            if (col < 128) {
                int ci = col >> 1;
                if (row  < NN) g_hf[(size_t)row  * 64 + ci] = pack_h2(acc[mi][j].x, acc[mi][j].y);
                if (row2 < NN) g_hf[(size_t)row2 * 64 + ci] = pack_h2(acc[mi][j].z, acc[mi][j].w);
            } else {
                int c = col - 128;
                if (row  < NN) *(float2*)(g_skip + (size_t)row  * 128 + c) =
                    make_float2(acc[mi][j].x, acc[mi][j].y);
                if (row2 < NN) *(float2*)(g_skip + (size_t)row2 * 128 + c) =
                    make_float2(acc[mi][j].z, acc[mi][j].w);
            }
        }
    }
}

// warp per node: per-head logits from fp16 h
__global__ void att_k(const float* __restrict__ asrc, const float* __restrict__ adst) {
    int g = blockIdx.x * blockDim.x + threadIdx.x;
    int n = g >> 5, lane = g & 31;
    if (n >= NN) return;
    float4 hv = unpack4(((const uint2*)(g_hf + (size_t)n * 64))[lane]);
    float4 vs = ((const float4*)asrc)[lane];
    float4 vd = ((const float4*)adst)[lane];
    float ps = hv.x * vs.x + hv.y * vs.y + hv.z * vs.z + hv.w * vs.w;
    float pd = hv.x * vd.x + hv.y * vd.y + hv.z * vd.z + hv.w * vd.w;
#pragma unroll
    for (int o = 4; o >= 1; o >>= 1) {
        ps += __shfl_down_sync(0xffffffff, ps, o);
        pd += __shfl_down_sync(0xffffffff, pd, o);
    }
    if ((lane & 7) == 0) {
        int h = lane >> 3;
        g_as[n * 4 + h] = ps;
        g_ad[n * 4 + h] = pd;
    }
}

// Fused CSR aggregation + softmax-norm + bias + skip + LayerNorm (warp/node)
__global__ void __launch_bounds__(256) eagg_k(const float* __restrict__ gb,
                                              const float* __restrict__ sb,
                                              const float* __restrict__ lg,
                                              const float* __restrict__ lb,
                                              float* __restrict__ out) {
    int g = blockIdx.x * blockDim.x + threadIdx.x;
    int n = g >> 5, lane = g & 31;
    if (n >= NN) return;
    int h = lane >> 3;

    float ad_h = g_ad[n * 4 + h];

    // self loop
    float p = __expf(lrelu(g_as[n * 4 + h] + ad_h));
    float4 hv = unpack4(((const uint2*)(g_hf + (size_t)n * 64))[lane]);
    float z = p;
    float4 acc = make_float4(p * hv.x, p * hv.y, p * hv.z, p * hv.w);

    int e   = g_off[n];
    int end = g_off[n + 1];
    for (; e + 4 <= end; e += 4) {
        int s0 = g_esrc[e], s1 = g_esrc[e + 1], s2 = g_esrc[e + 2], s3 = g_esrc[e + 3];
        float a0 = __ldg(g_as + s0 * 4 + h);
        float a1 = __ldg(g_as + s1 * 4 + h);
        float a2 = __ldg(g_as + s2 * 4 + h);
        float a3 = __ldg(g_as + s3 * 4 + h);
        uint2 w0 = ((const uint2*)(g_hf + (size_t)s0 * 64))[lane];
        uint2 w1 = ((const uint2*)(g_hf + (size_t)s1 * 64))[lane];
        uint2 w2 = ((const uint2*)(g_hf + (size_t)s2 * 64))[lane];
        uint2 w3 = ((const uint2*)(g_hf + (size_t)s3 * 64))[lane];
        float p0 = __expf(lrelu(a0 + ad_h));
        float p1 = __expf(lrelu(a1 + ad_h));
        float p2 = __expf(lrelu(a2 + ad_h));
        float p3 = __expf(lrelu(a3 + ad_h));
        z += (p0 + p1) + (p2 + p3);
        float4 h0 = unpack4(w0), h1 = unpack4(w1), h2 = unpack4(w2), h3 = unpack4(w3);
        acc.x += p0 * h0.x + p1 * h1.x + p2 * h2.x + p3 * h3.x;
        acc.y += p0 * h0.y + p1 * h1.y + p2 * h2.y + p3 * h3.y;
        acc.z += p0 * h0.z + p1 * h1.z + p2 * h2.z + p3 * h3.z;
        acc.w += p0 * h0.w + p1 * h1.w + p2 * h2.w + p3 * h3.w;
    }
    for (; e < end; e++) {
        int s0 = g_esrc[e];
        float a0 = __ldg(g_as + s0 * 4 + h);
        float4 h0 = unpack4(((const uint2*)(g_hf + (size_t)s0 * 64))[lane]);
        float p0 = __expf(lrelu(a0 + ad_h));
        z += p0;
        acc.x += p0 * h0.x; acc.y += p0 * h0.y;
        acc.z += p0 * h0.z; acc.w += p0 * h0.w;
    }

    float inv = 1.0f / (z + 1e-16f);
    float4 sk = ((const float4*)(g_skip + (size_t)n * 128))[lane];
    float4 b1 = ((const float4*)gb)[lane];
    float4 b2 = ((const float4*)sb)[lane];
    float4 v;
    v.x = acc.x * inv + sk.x + b1.x + b2.x;
    v.y = acc.y * inv + sk.y + b1.y + b2.y;
    v.z = acc.z * inv + sk.z + b1.z + b2.z;
    v.w = acc.w * inv + sk.w + b1.w + b2.w;

    float sum = v.x + v.y + v.z + v.w;
    float sq  = v.x * v.x + v.y * v.y + v.z * v.z + v.w * v.w;
#pragma unroll
    for (int o = 16; o >= 1; o >>= 1) {
        sum += __shfl_xor_sync(0xffffffff, sum, o);
        sq  += __shfl_xor_sync(0xffffffff, sq, o);
    }
    float mu  = sum * (1.0f / 128.0f);
    float var = sq * (1.0f / 128.0f) - mu * mu;
    float invs = rsqrtf(var + 1e-5f);
    float4 gg = ((const float4*)lg)[lane];
    float4 bb = ((const float4*)lb)[lane];
    float4 o4;
    o4.x = (v.x - mu) * invs * gg.x + bb.x;
    o4.y = (v.y - mu) * invs * gg.y + bb.y;
    o4.z = (v.z - mu) * invs * gg.z + bb.z;
    o4.w = (v.w - mu) * invs * gg.w + bb.w;
    ((float4*)(out + (size_t)n * 128))[lane] = o4;
}

// ---------------- stream setup (lazy, first kernel_launch call) ----------------
struct Streams {
    cudaStream_t s1 = 0;
    cudaEvent_t  ev0 = 0, ev1 = 0;
    bool ok = false;
    Streams() {
        ok = cudaStreamCreateWithFlags(&s1, cudaStreamNonBlocking) == cudaSuccess &&
             cudaEventCreateWithFlags(&ev0, cudaEventDisableTiming) == cudaSuccess &&
             cudaEventCreateWithFlags(&ev1, cudaEventDisableTiming) == cudaSuccess;
    }
};

// ---------------- launch ----------------
extern "C" void kernel_launch(void* const* d_in, const int* in_sizes, int n_in,
                              void* d_out, int out_size) {
    const float* x        = (const float*)d_in[0];
    const void*  ei       = d_in[1];
    const float* W        = (const float*)d_in[2];
    const float* att_src  = (const float*)d_in[3];
    const float* att_dst  = (const float*)d_in[4];
    const float* gat_bias = (const float*)d_in[5];
    const float* skip_W   = (const float*)d_in[6];
    const float* skip_b   = (const float*)d_in[7];
    const float* ln_g     = (const float*)d_in[8];
    const float* ln_b     = (const float*)d_in[9];
    float* out = (float*)d_out;

    int nblocks = (NN + 1023) / 1024;

    static Streams st;  // constructed on first call, after CUDA is initialized

    if (st.ok) {
        detect_k<<<1, 32>>>((const long long*)ei);
        wsplit_k<<<64, 256>>>(W, skip_W);
        cudaEventRecord(st.ev0, 0);
        cudaStreamWaitEvent(st.s1, st.ev0, 0);
        // side stream: CSR build (independent of gemm/att)
        init_k<<<(NN + 255) / 256, 256, 0, st.s1>>>();
        hist_k<<<(EE + 255) / 256, 256, 0, st.s1>>>(ei);
        scanA_k<<<nblocks, 1024, 0, st.s1>>>();
        scanB_k<<<1, 128, 0, st.s1>>>(nblocks);
        scanC_k<<<(NN + 255) / 256, 256, 0, st.s1>>>();
        scatter_k<<<(EE + 255) / 256, 256, 0, st.s1>>>(ei);
        cudaEventRecord(st.ev1, st.s1);
        // main stream: GEMM + logits
        gemm_bf16_k<<<(NN + BM - 1) / BM, 256>>>(x);
        att_k<<<(NN * 32 + 255) / 256, 256>>>(att_src, att_dst);
        cudaStreamWaitEvent(0, st.ev1, 0);
        eagg_k<<<(NN * 32 + 255) / 256, 256>>>(gat_bias, skip_b, ln_g, ln_b, out);
    } else {
        detect_k<<<1, 32>>>((const long long*)ei);
        wsplit_k<<<64, 256>>>(W, skip_W);
        init_k<<<(NN + 255) / 256, 256>>>();
        gemm_bf16_k<<<(NN + BM - 1) / BM, 256>>>(x);
        att_k<<<(NN * 32 + 255) / 256, 256>>>(att_src, att_dst);
        hist_k<<<(EE + 255) / 256, 256>>>(ei);
        scanA_k<<<nblocks, 1024>>>();
        scanB_k<<<1, 128>>>(nblocks);
        scanC_k<<<(NN + 255) / 256, 256>>>();
        scatter_k<<<(EE + 255) / 256, 256>>>(ei);
        eagg_k<<<(NN * 32 + 255) / 256, 256>>>(gat_bias, skip_b, ln_g, ln_b, out);
    }
}

// round 10
// speedup vs baseline: 4.8559x; 1.0232x over previous
#include <cuda_runtime.h>
#include <cuda_bf16.h>
#include <cuda_fp16.h>
#include <math.h>

#define NN    100000
#define EE    1600000
#define HH    4
#define DD    128
#define BM    64
#define BK    16

// ---------------- scratch (device globals) ----------------
__device__ unsigned g_hf[NN * 64];     // h as packed fp16x2 [N][64]
__device__ float    g_skip[NN * DD];   // x @ skip_W (fp32)
__device__ unsigned g_Wbh[64 * 256];   // W|skip_W bf16-hi, packed k-pairs [64][256]
__device__ unsigned g_Wbl[64 * 256];   // bf16-lo
__device__ float    g_as[NN * HH];
__device__ float    g_ad[NN * HH];
__device__ int      g_cnt[NN];
__device__ int      g_exc[NN];
__device__ int      g_bsum[128];
__device__ int      g_boff[128];
__device__ int      g_off[NN + 1];
__device__ int      g_cur[NN];
__device__ int      g_esrc[EE];
__device__ int      g_is64;

// ---------------- helpers ----------------
__device__ __forceinline__ float lrelu(float v) { return v > 0.0f ? v : 0.2f * v; }

__device__ __forceinline__ void mma_bf16(float4& c, const unsigned a[4],
                                         unsigned b0, unsigned b1) {
    asm volatile(
        "mma.sync.aligned.m16n8k16.row.col.f32.bf16.bf16.f32 "
        "{%0,%1,%2,%3}, {%4,%5,%6,%7}, {%8,%9}, {%0,%1,%2,%3};"
        : "+f"(c.x), "+f"(c.y), "+f"(c.z), "+f"(c.w)
        : "r"(a[0]), "r"(a[1]), "r"(a[2]), "r"(a[3]), "r"(b0), "r"(b1));
}

__device__ __forceinline__ unsigned pack_bf2(float a, float b) {
    __nv_bfloat162 r = __floats2bfloat162_rn(a, b);
    return *(unsigned*)&r;
}
__device__ __forceinline__ unsigned pack_h2(float a, float b) {
    __half2 r = __floats2half2_rn(a, b);
    return *(unsigned*)&r;
}

__device__ __forceinline__ void cp16(unsigned* dst_smem, const unsigned* src) {
    unsigned d = (unsigned)__cvta_generic_to_shared(dst_smem);
    asm volatile("cp.async.cg.shared.global [%0], [%1], 16;" :: "r"(d), "l"(src));
}

__device__ __forceinline__ int load_dst(const void* ei, int i) {
    return g_is64 ? (int)((const long long*)ei)[EE + i] : ((const int*)ei)[EE + i];
}
__device__ __forceinline__ void load_edge(const void* ei, int i, int& s, int& d) {
    if (g_is64) {
        const long long* p = (const long long*)ei;
        s = (int)p[i]; d = (int)p[EE + i];
    } else {
        const int* p = (const int*)ei;
        s = p[i]; d = p[EE + i];
    }
}

__device__ __forceinline__ float4 unpack4(uint2 w) {
    float2 f0 = __half22float2(*(__half2*)&w.x);
    float2 f1 = __half22float2(*(__half2*)&w.y);
    return make_float4(f0.x, f0.y, f1.x, f1.y);
}

// ---------------- kernels ----------------
__global__ void detect_k(const long long* ei) {
    if (blockIdx.x == 0 && threadIdx.x == 0) {
        int ok64 = 1;
        for (int i = 0; i < 64; i++) {
            long long v = ei[i];
            if (v < 0 || v >= NN) { ok64 = 0; break; }
        }
        g_is64 = ok64;
    }
}

// split [W | skip_W] -> bf16 hi/lo, packed k-pairs: [64 kp][256 n]
__global__ void wsplit_k(const float* __restrict__ W, const float* __restrict__ sW) {
    int i = blockIdx.x * blockDim.x + threadIdx.x;
    if (i >= 64 * 256) return;
    int kp = i >> 8, c = i & 255;
    float v0, v1;
    if (c < 128) { v0 = W[(2 * kp) * 128 + c];        v1 = W[(2 * kp + 1) * 128 + c]; }
    else         { v0 = sW[(2 * kp) * 128 + c - 128]; v1 = sW[(2 * kp + 1) * 128 + c - 128]; }
    float h0 = __bfloat162float(__float2bfloat16_rn(v0));
    float h1 = __bfloat162float(__float2bfloat16_rn(v1));
    g_Wbh[i] = pack_bf2(v0, v1);
    g_Wbl[i] = pack_bf2(v0 - h0, v1 - h1);
}

__global__ void init_k() {
    int i = blockIdx.x * blockDim.x + threadIdx.x;
    if (i < NN) g_cnt[i] = 0;
}

__global__ void hist_k(const void* __restrict__ ei) {
    int i = blockIdx.x * blockDim.x + threadIdx.x;
    if (i >= EE) return;
    atomicAdd(&g_cnt[load_dst(ei, i)], 1);
}

__global__ void __launch_bounds__(1024) scanA_k() {
    __shared__ int sd[1024];
    int t = threadIdx.x;
    int i = blockIdx.x * 1024 + t;
    int v = (i < NN) ? g_cnt[i] : 0;
    sd[t] = v;
    __syncthreads();
#pragma unroll
    for (int o = 1; o < 1024; o <<= 1) {
        int x = (t >= o) ? sd[t - o] : 0;
        __syncthreads();
        sd[t] += x;
        __syncthreads();
    }
    if (i < NN) g_exc[i] = sd[t] - v;
    if (t == 1023) g_bsum[blockIdx.x] = sd[t];
}

__global__ void scanB_k(int nblocks) {
    __shared__ int sd[128];
    int t = threadIdx.x;
    int v = (t < nblocks) ? g_bsum[t] : 0;
    sd[t] = v;
    __syncthreads();
#pragma unroll
    for (int o = 1; o < 128; o <<= 1) {
        int x = (t >= o) ? sd[t - o] : 0;
        __syncthreads();
        sd[t] += x;
        __syncthreads();
    }
    g_boff[t] = sd[t] - v;
}

__global__ void scanC_k() {
    int i = blockIdx.x * blockDim.x + threadIdx.x;
    if (i < NN) {
        int off = g_exc[i] + g_boff[i >> 10];
        g_off[i] = off;
        g_cur[i] = off;
    }
    if (i == 0) g_off[NN] = EE;
}

__global__ void scatter_k(const void* __restrict__ ei) {
    int i = blockIdx.x * blockDim.x + threadIdx.x;
    if (i >= EE) return;
    int s, d;
    load_edge(ei, i, s, d);
    int pos = atomicAdd(&g_cur[d], 1);
    g_esrc[pos] = s;
}

// bf16 split GEMM, occupancy-oriented: tile M=64, N=128 per block.
// blockIdx.y = 0: h-half (cols 0..127) -> g_hf + fused att logits
// blockIdx.y = 1: skip-half (cols 128..255) -> g_skip
// 8 warps (2m x 4n), warp tile 32x32; per-thread acc = 32 fp32.
#define XP 12    // A smem pitch in u32
#define WP 136   // B smem pitch in u32
__global__ void __launch_bounds__(256, 3) gemm_bf16_k(const float* __restrict__ x,
                                                      const float* __restrict__ asrc,
                                                      const float* __restrict__ adst) {
    __shared__ __align__(16) unsigned xs_h[2][BM * XP], xs_l[2][BM * XP];
    __shared__ __align__(16) unsigned ws_h[2][8 * WP],  ws_l[2][8 * WP];
    int t = threadIdx.x;
    int wid = t >> 5, lane = t & 31;
    int gid = lane >> 2, tig = lane & 3;
    int wm = wid >> 2, wn = wid & 3;
    int m0 = blockIdx.x * BM;
    int half = blockIdx.y;          // 0: h, 1: skip
    int ncol0 = half * 128;         // W column offset

    int xrow = t >> 2;              // x staging: row 0..63
    int xq   = t & 3;               // k-quarter
    int wr   = t >> 5;              // W staging: kp row 0..7
    int wc4  = (t & 31) * 4;        // uint4 col

    float4 acc[2][4];
#pragma unroll
    for (int mi = 0; mi < 2; mi++)
#pragma unroll
        for (int j = 0; j < 4; j++) acc[mi][j] = make_float4(0.f, 0.f, 0.f, 0.f);

    // ---- prologue: stage tile 0 ----
    {
        cp16(&ws_h[0][wr * WP + wc4], &g_Wbh[wr * 256 + ncol0 + wc4]);
        cp16(&ws_l[0][wr * WP + wc4], &g_Wbl[wr * 256 + ncol0 + wc4]);
        asm volatile("cp.async.commit_group;");
        float4 v = make_float4(0.f, 0.f, 0.f, 0.f);
        if (m0 + xrow < NN)
            v = *(const float4*)(x + (size_t)(m0 + xrow) * 128 + xq * 4);
        float hx = __bfloat162float(__float2bfloat16_rn(v.x));
        float hy = __bfloat162float(__float2bfloat16_rn(v.y));
        float hz = __bfloat162float(__float2bfloat16_rn(v.z));
        float hw = __bfloat162float(__float2bfloat16_rn(v.w));
        int b = xrow * XP + xq * 2;
        xs_h[0][b]     = pack_bf2(v.x, v.y);
        xs_h[0][b + 1] = pack_bf2(v.z, v.w);
        xs_l[0][b]     = pack_bf2(v.x - hx, v.y - hy);
        xs_l[0][b + 1] = pack_bf2(v.z - hz, v.w - hw);
        asm volatile("cp.async.wait_group 0;");
        __syncthreads();
    }

    for (int it = 0; it < 8; it++) {
        int cur = it & 1, nxt = cur ^ 1;
        float4 v;
        bool more = (it < 7);
        if (more) {
            int kp0 = ((it + 1) * BK) >> 1;
            cp16(&ws_h[nxt][wr * WP + wc4], &g_Wbh[(kp0 + wr) * 256 + ncol0 + wc4]);
            cp16(&ws_l[nxt][wr * WP + wc4], &g_Wbl[(kp0 + wr) * 256 + ncol0 + wc4]);
            asm volatile("cp.async.commit_group;");
            v = make_float4(0.f, 0.f, 0.f, 0.f);
            if (m0 + xrow < NN)
                v = *(const float4*)(x + (size_t)(m0 + xrow) * 128 + (it + 1) * BK + xq * 4);
        }

        unsigned ah[2][4], al[2][4];
#pragma unroll
        for (int mi = 0; mi < 2; mi++) {
            int rb = wm * 32 + mi * 16 + gid;
            ah[mi][0] = xs_h[cur][rb * XP + tig];
            ah[mi][1] = xs_h[cur][(rb + 8) * XP + tig];
            ah[mi][2] = xs_h[cur][rb * XP + tig + 4];
            ah[mi][3] = xs_h[cur][(rb + 8) * XP + tig + 4];
            al[mi][0] = xs_l[cur][rb * XP + tig];
            al[mi][1] = xs_l[cur][(rb + 8) * XP + tig];
            al[mi][2] = xs_l[cur][rb * XP + tig + 4];
            al[mi][3] = xs_l[cur][(rb + 8) * XP + tig + 4];
        }
#pragma unroll
        for (int j = 0; j < 4; j++) {
            int col = wn * 32 + j * 8 + gid;
            unsigned bh0 = ws_h[cur][tig * WP + col];
            unsigned bh1 = ws_h[cur][(tig + 4) * WP + col];
            unsigned bl0 = ws_l[cur][tig * WP + col];
            unsigned bl1 = ws_l[cur][(tig + 4) * WP + col];
#pragma unroll
            for (int mi = 0; mi < 2; mi++) {
                mma_bf16(acc[mi][j], ah[mi], bh0, bh1);
                mma_bf16(acc[mi][j], al[mi], bh0, bh1);
                mma_bf16(acc[mi][j], ah[mi], bl0, bl1);
            }
        }

        if (more) {
            float hx = __bfloat162float(__float2bfloat16_rn(v.x));
            float hy = __bfloat162float(__float2bfloat16_rn(v.y));
            float hz = __bfloat162float(__float2bfloat16_rn(v.z));
            float hw = __bfloat162float(__float2bfloat16_rn(v.w));
            int b = xrow * XP + xq * 2;
            xs_h[nxt][b]     = pack_bf2(v.x, v.y);
            xs_h[nxt][b + 1] = pack_bf2(v.z, v.w);
            xs_l[nxt][b]     = pack_bf2(v.x - hx, v.y - hy);
            xs_l[nxt][b + 1] = pack_bf2(v.z - hz, v.w - hw);
            asm volatile("cp.async.wait_group 0;");
            __syncthreads();
        }
    }

    if (half == 0) {
        // ---- h-half epilogue: store fp16x2 + fused att logits (head = wn) ----
#pragma unroll
        for (int mi = 0; mi < 2; mi++) {
            int row  = m0 + wm * 32 + mi * 16 + gid;
            int row2 = row + 8;
            float ps0 = 0.f, pd0 = 0.f, ps1 = 0.f, pd1 = 0.f;
#pragma unroll
            for (int j = 0; j < 4; j++) {
                int col = wn * 32 + j * 8 + tig * 2;
                if (row  < NN) g_hf[(size_t)row  * 64 + (col >> 1)] =
                    pack_h2(acc[mi][j].x, acc[mi][j].y);
                if (row2 < NN) g_hf[(size_t)row2 * 64 + (col >> 1)] =
                    pack_h2(acc[mi][j].z, acc[mi][j].w);
                float as0 = asrc[col], as1 = asrc[col + 1];
                float ad0 = adst[col], ad1 = adst[col + 1];
                ps0 += acc[mi][j].x * as0 + acc[mi][j].y * as1;
                pd0 += acc[mi][j].x * ad0 + acc[mi][j].y * ad1;
                ps1 += acc[mi][j].z * as0 + acc[mi][j].w * as1;
                pd1 += acc[mi][j].z * ad0 + acc[mi][j].w * ad1;
            }
            // reduce over tig (lanes gid*4 + 0..3)
#pragma unroll
            for (int o = 1; o <= 2; o <<= 1) {
                ps0 += __shfl_xor_sync(0xffffffff, ps0, o);
                pd0 += __shfl_xor_sync(0xffffffff, pd0, o);
                ps1 += __shfl_xor_sync(0xffffffff, ps1, o);
                pd1 += __shfl_xor_sync(0xffffffff, pd1, o);
            }
            if (tig == 0) {
                if (row < NN)  { g_as[row * 4 + wn]  = ps0; g_ad[row * 4 + wn]  = pd0; }
                if (row2 < NN) { g_as[row2 * 4 + wn] = ps1; g_ad[row2 * 4 + wn] = pd1; }
            }
        }
    } else {
        // ---- skip-half epilogue: fp32 store ----
#pragma unroll
        for (int mi = 0; mi < 2; mi++) {
#pragma unroll
            for (int j = 0; j < 4; j++) {
                int col  = wn * 32 + j * 8 + tig * 2;
                int row  = m0 + wm * 32 + mi * 16 + gid;
                int row2 = row + 8;
                if (row  < NN) *(float2*)(g_skip + (size_t)row  * 128 + col) =
                    make_float2(acc[mi][j].x, acc[mi][j].y);
                if (row2 < NN) *(float2*)(g_skip + (size_t)row2 * 128 + col) =
                    make_float2(acc[mi][j].z, acc[mi][j].w);
            }
        }
    }
}

// Fused CSR aggregation + softmax-norm + bias + skip + LayerNorm (warp/node)
__global__ void __launch_bounds__(256) eagg_k(const float* __restrict__ gb,
                                              const float* __restrict__ sb,
                                              const float* __restrict__ lg,
                                              const float* __restrict__ lb,
                                              float* __restrict__ out) {
    int g = blockIdx.x * blockDim.x + threadIdx.x;
    int n = g >> 5, lane = g & 31;
    if (n >= NN) return;
    int h = lane >> 3;

    float ad_h = g_ad[n * 4 + h];

    // self loop
    float p = __expf(lrelu(g_as[n * 4 + h] + ad_h));
    float4 hv = unpack4(((const uint2*)(g_hf + (size_t)n * 64))[lane]);
    float z = p;
    float4 acc = make_float4(p * hv.x, p * hv.y, p * hv.z, p * hv.w);

    int e   = g_off[n];
    int end = g_off[n + 1];
    for (; e + 4 <= end; e += 4) {
        int s0 = g_esrc[e], s1 = g_esrc[e + 1], s2 = g_esrc[e + 2], s3 = g_esrc[e + 3];
        float a0 = __ldg(g_as + s0 * 4 + h);
        float a1 = __ldg(g_as + s1 * 4 + h);
        float a2 = __ldg(g_as + s2 * 4 + h);
        float a3 = __ldg(g_as + s3 * 4 + h);
        uint2 w0 = ((const uint2*)(g_hf + (size_t)s0 * 64))[lane];
        uint2 w1 = ((const uint2*)(g_hf + (size_t)s1 * 64))[lane];
        uint2 w2 = ((const uint2*)(g_hf + (size_t)s2 * 64))[lane];
        uint2 w3 = ((const uint2*)(g_hf + (size_t)s3 * 64))[lane];
        float p0 = __expf(lrelu(a0 + ad_h));
        float p1 = __expf(lrelu(a1 + ad_h));
        float p2 = __expf(lrelu(a2 + ad_h));
        float p3 = __expf(lrelu(a3 + ad_h));
        z += (p0 + p1) + (p2 + p3);
        float4 h0 = unpack4(w0), h1 = unpack4(w1), h2 = unpack4(w2), h3 = unpack4(w3);
        acc.x += p0 * h0.x + p1 * h1.x + p2 * h2.x + p3 * h3.x;
        acc.y += p0 * h0.y + p1 * h1.y + p2 * h2.y + p3 * h3.y;
        acc.z += p0 * h0.z + p1 * h1.z + p2 * h2.z + p3 * h3.z;
        acc.w += p0 * h0.w + p1 * h1.w + p2 * h2.w + p3 * h3.w;
    }
    for (; e < end; e++) {
        int s0 = g_esrc[e];
        float a0 = __ldg(g_as + s0 * 4 + h);
        float4 h0 = unpack4(((const uint2*)(g_hf + (size_t)s0 * 64))[lane]);
        float p0 = __expf(lrelu(a0 + ad_h));
        z += p0;
        acc.x += p0 * h0.x; acc.y += p0 * h0.y;
        acc.z += p0 * h0.z; acc.w += p0 * h0.w;
    }

    float inv = 1.0f / (z + 1e-16f);
    float4 sk = ((const float4*)(g_skip + (size_t)n * 128))[lane];
    float4 b1 = ((const float4*)gb)[lane];
    float4 b2 = ((const float4*)sb)[lane];
    float4 v;
    v.x = acc.x * inv + sk.x + b1.x + b2.x;
    v.y = acc.y * inv + sk.y + b1.y + b2.y;
    v.z = acc.z * inv + sk.z + b1.z + b2.z;
    v.w = acc.w * inv + sk.w + b1.w + b2.w;

    float sum = v.x + v.y + v.z + v.w;
    float sq  = v.x * v.x + v.y * v.y + v.z * v.z + v.w * v.w;
#pragma unroll
    for (int o = 16; o >= 1; o >>= 1) {
        sum += __shfl_xor_sync(0xffffffff, sum, o);
        sq  += __shfl_xor_sync(0xffffffff, sq, o);
    }
    float mu  = sum * (1.0f / 128.0f);
    float var = sq * (1.0f / 128.0f) - mu * mu;
    float invs = rsqrtf(var + 1e-5f);
    float4 gg = ((const float4*)lg)[lane];
    float4 bb = ((const float4*)lb)[lane];
    float4 o4;
    o4.x = (v.x - mu) * invs * gg.x + bb.x;
    o4.y = (v.y - mu) * invs * gg.y + bb.y;
    o4.z = (v.z - mu) * invs * gg.z + bb.z;
    o4.w = (v.w - mu) * invs * gg.w + bb.w;
    ((float4*)(out + (size_t)n * 128))[lane] = o4;
}

// ---------------- stream setup (lazy, first kernel_launch call) ----------------
struct Streams {
    cudaStream_t s1 = 0;
    cudaEvent_t  ev0 = 0, ev1 = 0;
    bool ok = false;
    Streams() {
        ok = cudaStreamCreateWithFlags(&s1, cudaStreamNonBlocking) == cudaSuccess &&
             cudaEventCreateWithFlags(&ev0, cudaEventDisableTiming) == cudaSuccess &&
             cudaEventCreateWithFlags(&ev1, cudaEventDisableTiming) == cudaSuccess;
    }
};

// ---------------- launch ----------------
extern "C" void kernel_launch(void* const* d_in, const int* in_sizes, int n_in,
                              void* d_out, int out_size) {
    const float* x        = (const float*)d_in[0];
    const void*  ei       = d_in[1];
    const float* W        = (const float*)d_in[2];
    const float* att_src  = (const float*)d_in[3];
    const float* att_dst  = (const float*)d_in[4];
    const float* gat_bias = (const float*)d_in[5];
    const float* skip_W   = (const float*)d_in[6];
    const float* skip_b   = (const float*)d_in[7];
    const float* ln_g     = (const float*)d_in[8];
    const float* ln_b     = (const float*)d_in[9];
    float* out = (float*)d_out;

    int nblocks = (NN + 1023) / 1024;
    dim3 ggrid((NN + BM - 1) / BM, 2);

    static Streams st;  // constructed on first call, after CUDA is initialized

    if (st.ok) {
        detect_k<<<1, 32>>>((const long long*)ei);
        wsplit_k<<<64, 256>>>(W, skip_W);
        cudaEventRecord(st.ev0, 0);
        cudaStreamWaitEvent(st.s1, st.ev0, 0);
        // side stream: CSR build (independent of gemm)
        init_k<<<(NN + 255) / 256, 256, 0, st.s1>>>();
        hist_k<<<(EE + 255) / 256, 256, 0, st.s1>>>(ei);
        scanA_k<<<nblocks, 1024, 0, st.s1>>>();
        scanB_k<<<1, 128, 0, st.s1>>>(nblocks);
        scanC_k<<<(NN + 255) / 256, 256, 0, st.s1>>>();
        scatter_k<<<(EE + 255) / 256, 256, 0, st.s1>>>(ei);
        cudaEventRecord(st.ev1, st.s1);
        // main stream: GEMM (+fused att logits)
        gemm_bf16_k<<<ggrid, 256>>>(x, att_src, att_dst);
        cudaStreamWaitEvent(0, st.ev1, 0);
        eagg_k<<<(NN * 32 + 255) / 256, 256>>>(gat_bias, skip_b, ln_g, ln_b, out);
    } else {
        detect_k<<<1, 32>>>((const long long*)ei);
        wsplit_k<<<64, 256>>>(W, skip_W);
        init_k<<<(NN + 255) / 256, 256>>>();
        gemm_bf16_k<<<ggrid, 256>>>(x, att_src, att_dst);
        hist_k<<<(EE + 255) / 256, 256>>>(ei);
        scanA_k<<<nblocks, 1024>>>();
        scanB_k<<<1, 128>>>(nblocks);
        scanC_k<<<(NN + 255) / 256, 256>>>();
        scatter_k<<<(EE + 255) / 256, 256>>>(ei);
        eagg_k<<<(NN * 32 + 255) / 256, 256>>>(gat_bias, skip_b, ln_g, ln_b, out);
    }
}

// round 12
// speedup vs baseline: 4.8568x; 1.0002x over previous
#include <cuda_runtime.h>
#include <cuda_bf16.h>
#include <cuda_fp16.h>
#include <math.h>

#define NN    100000
#define EE    1600000
#define HH    4
#define DD    128
#define BM    64
#define BK    16

// ---------------- scratch (device globals) ----------------
__device__ unsigned g_hf[NN * 64];     // h as packed fp16x2 [N][64]
__device__ float    g_skip[NN * DD];   // x @ skip_W (fp32)
__device__ unsigned g_Wbh[64 * 256];   // W|skip_W bf16-hi, packed k-pairs [64][256]
__device__ unsigned g_Wbl[64 * 256];   // bf16-lo
__device__ float    g_as[NN * HH];
__device__ float    g_ad[NN * HH];
__device__ int      g_cnt[NN];
__device__ int      g_exc[NN];
__device__ int      g_bsum[128];
__device__ int      g_boff[128];
__device__ int      g_off[NN + 1];
__device__ int      g_cur[NN];
__device__ int      g_esrc[EE];
__device__ int      g_is64;

// ---------------- helpers ----------------
__device__ __forceinline__ float lrelu(float v) { return v > 0.0f ? v : 0.2f * v; }

__device__ __forceinline__ void mma_bf16(float4& c, const unsigned a[4],
                                         unsigned b0, unsigned b1) {
    asm volatile(
        "mma.sync.aligned.m16n8k16.row.col.f32.bf16.bf16.f32 "
        "{%0,%1,%2,%3}, {%4,%5,%6,%7}, {%8,%9}, {%0,%1,%2,%3};"
        : "+f"(c.x), "+f"(c.y), "+f"(c.z), "+f"(c.w)
        : "r"(a[0]), "r"(a[1]), "r"(a[2]), "r"(a[3]), "r"(b0), "r"(b1));
}

__device__ __forceinline__ unsigned pack_bf2(float a, float b) {
    __nv_bfloat162 r = __floats2bfloat162_rn(a, b);
    return *(unsigned*)&r;
}
__device__ __forceinline__ unsigned pack_h2(float a, float b) {
    __half2 r = __floats2half2_rn(a, b);
    return *(unsigned*)&r;
}

__device__ __forceinline__ void cp16(unsigned* dst_smem, const unsigned* src) {
    unsigned d = (unsigned)__cvta_generic_to_shared(dst_smem);
    asm volatile("cp.async.cg.shared.global [%0], [%1], 16;" :: "r"(d), "l"(src));
}

__device__ __forceinline__ float4 unpack4(uint2 w) {
    float2 f0 = __half22float2(*(__half2*)&w.x);
    float2 f1 = __half22float2(*(__half2*)&w.y);
    return make_float4(f0.x, f0.y, f1.x, f1.y);
}

// ---------------- kernels ----------------
__global__ void detect_k(const long long* ei) {
    if (blockIdx.x == 0 && threadIdx.x == 0) {
        int ok64 = 1;
        for (int i = 0; i < 64; i++) {
            long long v = ei[i];
            if (v < 0 || v >= NN) { ok64 = 0; break; }
        }
        g_is64 = ok64;
    }
}

// split [W | skip_W] -> bf16 hi/lo, packed k-pairs: [64 kp][256 n]
__global__ void wsplit_k(const float* __restrict__ W, const float* __restrict__ sW) {
    int i = blockIdx.x * blockDim.x + threadIdx.x;
    if (i >= 64 * 256) return;
    int kp = i >> 8, c = i & 255;
    float v0, v1;
    if (c < 128) { v0 = W[(2 * kp) * 128 + c];        v1 = W[(2 * kp + 1) * 128 + c]; }
    else         { v0 = sW[(2 * kp) * 128 + c - 128]; v1 = sW[(2 * kp + 1) * 128 + c - 128]; }
    float h0 = __bfloat162float(__float2bfloat16_rn(v0));
    float h1 = __bfloat162float(__float2bfloat16_rn(v1));
    g_Wbh[i] = pack_bf2(v0, v1);
    g_Wbl[i] = pack_bf2(v0 - h0, v1 - h1);
}

__global__ void init_k() {
    int i = blockIdx.x * blockDim.x + threadIdx.x;
    if (i < NN) g_cnt[i] = 0;
}

// 2 edges per thread, vectorized dst loads
__global__ void hist_k(const void* __restrict__ ei) {
    int i = (blockIdx.x * blockDim.x + threadIdx.x) * 2;
    if (i >= EE) return;
    if (g_is64) {
        longlong2 v = *(const longlong2*)((const long long*)ei + EE + i);
        atomicAdd(&g_cnt[(int)v.x], 1);
        atomicAdd(&g_cnt[(int)v.y], 1);
    } else {
        int2 v = *(const int2*)((const int*)ei + EE + i);
        atomicAdd(&g_cnt[v.x], 1);
        atomicAdd(&g_cnt[v.y], 1);
    }
}

__global__ void __launch_bounds__(1024) scanA_k() {
    __shared__ int sd[1024];
    int t = threadIdx.x;
    int i = blockIdx.x * 1024 + t;
    int v = (i < NN) ? g_cnt[i] : 0;
    sd[t] = v;
    __syncthreads();
#pragma unroll
    for (int o = 1; o < 1024; o <<= 1) {
        int x = (t >= o) ? sd[t - o] : 0;
        __syncthreads();
        sd[t] += x;
        __syncthreads();
    }
    if (i < NN) g_exc[i] = sd[t] - v;
    if (t == 1023) g_bsum[blockIdx.x] = sd[t];
}

__global__ void scanB_k(int nblocks) {
    __shared__ int sd[128];
    int t = threadIdx.x;
    int v = (t < nblocks) ? g_bsum[t] : 0;
    sd[t] = v;
    __syncthreads();
#pragma unroll
    for (int o = 1; o < 128; o <<= 1) {
        int x = (t >= o) ? sd[t - o] : 0;
        __syncthreads();
        sd[t] += x;
        __syncthreads();
    }
    g_boff[t] = sd[t] - v;
}

__global__ void scanC_k() {
    int i = blockIdx.x * blockDim.x + threadIdx.x;
    if (i < NN) {
        int off = g_exc[i] + g_boff[i >> 10];
        g_off[i] = off;
        g_cur[i] = off;
    }
    if (i == 0) g_off[NN] = EE;
}

// scatter a sub-range [e0, e1) of edges; 2 edges per thread
__global__ void scatter_k(const void* __restrict__ ei, int e0, int e1) {
    int i = e0 + (blockIdx.x * blockDim.x + threadIdx.x) * 2;
    if (i >= e1) return;
    int s0, d0, s1, d1;
    if (g_is64) {
        const long long* p = (const long long*)ei;
        longlong2 sv = *(const longlong2*)(p + i);
        longlong2 dv = *(const longlong2*)(p + EE + i);
        s0 = (int)sv.x; s1 = (int)sv.y; d0 = (int)dv.x; d1 = (int)dv.y;
    } else {
        const int* p = (const int*)ei;
        int2 sv = *(const int2*)(p + i);
        int2 dv = *(const int2*)(p + EE + i);
        s0 = sv.x; s1 = sv.y; d0 = dv.x; d1 = dv.y;
    }
    g_esrc[atomicAdd(&g_cur[d0], 1)] = s0;
    if (i + 1 < e1) g_esrc[atomicAdd(&g_cur[d1], 1)] = s1;
}

// bf16 split GEMM, occupancy-oriented: tile M=64, N=128 per block.
// blockIdx.y = 0: h-half -> g_hf + fused att logits; 1: skip-half -> g_skip
#define XP 12    // A smem pitch in u32
#define WP 136   // B smem pitch in u32
__global__ void __launch_bounds__(256, 3) gemm_bf16_k(const float* __restrict__ x,
                                                      const float* __restrict__ asrc,
                                                      const float* __restrict__ adst) {
    __shared__ __align__(16) unsigned xs_h[2][BM * XP], xs_l[2][BM * XP];
    __shared__ __align__(16) unsigned ws_h[2][8 * WP],  ws_l[2][8 * WP];
    int t = threadIdx.x;
    int wid = t >> 5, lane = t & 31;
    int gid = lane >> 2, tig = lane & 3;
    int wm = wid >> 2, wn = wid & 3;
    int m0 = blockIdx.x * BM;
    int half = blockIdx.y;
    int ncol0 = half * 128;

    int xrow = t >> 2;
    int xq   = t & 3;
    int wr   = t >> 5;
    int wc4  = (t & 31) * 4;

    float4 acc[2][4];
#pragma unroll
    for (int mi = 0; mi < 2; mi++)
#pragma unroll
        for (int j = 0; j < 4; j++) acc[mi][j] = make_float4(0.f, 0.f, 0.f, 0.f);

    // ---- prologue ----
    {
        cp16(&ws_h[0][wr * WP + wc4], &g_Wbh[wr * 256 + ncol0 + wc4]);
        cp16(&ws_l[0][wr * WP + wc4], &g_Wbl[wr * 256 + ncol0 + wc4]);
        asm volatile("cp.async.commit_group;");
        float4 v = make_float4(0.f, 0.f, 0.f, 0.f);
        if (m0 + xrow < NN)
            v = *(const float4*)(x + (size_t)(m0 + xrow) * 128 + xq * 4);
        float hx = __bfloat162float(__float2bfloat16_rn(v.x));
        float hy = __bfloat162float(__float2bfloat16_rn(v.y));
        float hz = __bfloat162float(__float2bfloat16_rn(v.z));
        float hw = __bfloat162float(__float2bfloat16_rn(v.w));
        int b = xrow * XP + xq * 2;
        xs_h[0][b]     = pack_bf2(v.x, v.y);
        xs_h[0][b + 1] = pack_bf2(v.z, v.w);
        xs_l[0][b]     = pack_bf2(v.x - hx, v.y - hy);
        xs_l[0][b + 1] = pack_bf2(v.z - hz, v.w - hw);
        asm volatile("cp.async.wait_group 0;");
        __syncthreads();
    }

    for (int it = 0; it < 8; it++) {
        int cur = it & 1, nxt = cur ^ 1;
        float4 v;
        bool more = (it < 7);
        if (more) {
            int kp0 = ((it + 1) * BK) >> 1;
            cp16(&ws_h[nxt][wr * WP + wc4], &g_Wbh[(kp0 + wr) * 256 + ncol0 + wc4]);
            cp16(&ws_l[nxt][wr * WP + wc4], &g_Wbl[(kp0 + wr) * 256 + ncol0 + wc4]);
            asm volatile("cp.async.commit_group;");
            v = make_float4(0.f, 0.f, 0.f, 0.f);
            if (m0 + xrow < NN)
                v = *(const float4*)(x + (size_t)(m0 + xrow) * 128 + (it + 1) * BK + xq * 4);
        }

        unsigned ah[2][4], al[2][4];
#pragma unroll
        for (int mi = 0; mi < 2; mi++) {
            int rb = wm * 32 + mi * 16 + gid;
            ah[mi][0] = xs_h[cur][rb * XP + tig];
            ah[mi][1] = xs_h[cur][(rb + 8) * XP + tig];
            ah[mi][2] = xs_h[cur][rb * XP + tig + 4];
            ah[mi][3] = xs_h[cur][(rb + 8) * XP + tig + 4];
            al[mi][0] = xs_l[cur][rb * XP + tig];
            al[mi][1] = xs_l[cur][(rb + 8) * XP + tig];
            al[mi][2] = xs_l[cur][rb * XP + tig + 4];
            al[mi][3] = xs_l[cur][(rb + 8) * XP + tig + 4];
        }
#pragma unroll
        for (int j = 0; j < 4; j++) {
            int col = wn * 32 + j * 8 + gid;
            unsigned bh0 = ws_h[cur][tig * WP + col];
            unsigned bh1 = ws_h[cur][(tig + 4) * WP + col];
            unsigned bl0 = ws_l[cur][tig * WP + col];
            unsigned bl1 = ws_l[cur][(tig + 4) * WP + col];
#pragma unroll
            for (int mi = 0; mi < 2; mi++) {
                mma_bf16(acc[mi][j], ah[mi], bh0, bh1);
                mma_bf16(acc[mi][j], al[mi], bh0, bh1);
                mma_bf16(acc[mi][j], ah[mi], bl0, bl1);
            }
        }

        if (more) {
            float hx = __bfloat162float(__float2bfloat16_rn(v.x));
            float hy = __bfloat162float(__float2bfloat16_rn(v.y));
            float hz = __bfloat162float(__float2bfloat16_rn(v.z));
            float hw = __bfloat162float(__float2bfloat16_rn(v.w));
            int b = xrow * XP + xq * 2;
            xs_h[nxt][b]     = pack_bf2(v.x, v.y);
            xs_h[nxt][b + 1] = pack_bf2(v.z, v.w);
            xs_l[nxt][b]     = pack_bf2(v.x - hx, v.y - hy);
            xs_l[nxt][b + 1] = pack_bf2(v.z - hz, v.w - hw);
            asm volatile("cp.async.wait_group 0;");
            __syncthreads();
        }
    }

    if (half == 0) {
#pragma unroll
        for (int mi = 0; mi < 2; mi++) {
            int row  = m0 + wm * 32 + mi * 16 + gid;
            int row2 = row + 8;
            float ps0 = 0.f, pd0 = 0.f, ps1 = 0.f, pd1 = 0.f;
#pragma unroll
            for (int j = 0; j < 4; j++) {
                int col = wn * 32 + j * 8 + tig * 2;
                if (row  < NN) g_hf[(size_t)row  * 64 + (col >> 1)] =
                    pack_h2(acc[mi][j].x, acc[mi][j].y);
                if (row2 < NN) g_hf[(size_t)row2 * 64 + (col >> 1)] =
                    pack_h2(acc[mi][j].z, acc[mi][j].w);
                float as0 = asrc[col], as1 = asrc[col + 1];
                float ad0 = adst[col], ad1 = adst[col + 1];
                ps0 += acc[mi][j].x * as0 + acc[mi][j].y * as1;
                pd0 += acc[mi][j].x * ad0 + acc[mi][j].y * ad1;
                ps1 += acc[mi][j].z * as0 + acc[mi][j].w * as1;
                pd1 += acc[mi][j].z * ad0 + acc[mi][j].w * ad1;
            }
#pragma unroll
            for (int o = 1; o <= 2; o <<= 1) {
                ps0 += __shfl_xor_sync(0xffffffff, ps0, o);
                pd0 += __shfl_xor_sync(0xffffffff, pd0, o);
                ps1 += __shfl_xor_sync(0xffffffff, ps1, o);
                pd1 += __shfl_xor_sync(0xffffffff, pd1, o);
            }
            if (tig == 0) {
                if (row < NN)  { g_as[row * 4 + wn]  = ps0; g_ad[row * 4 + wn]  = pd0; }
                if (row2 < NN) { g_as[row2 * 4 + wn] = ps1; g_ad[row2 * 4 + wn] = pd1; }
            }
        }
    } else {
#pragma unroll
        for (int mi = 0; mi < 2; mi++) {
#pragma unroll
            for (int j = 0; j < 4; j++) {
                int col  = wn * 32 + j * 8 + tig * 2;
                int row  = m0 + wm * 32 + mi * 16 + gid;
                int row2 = row + 8;
                if (row  < NN) *(float2*)(g_skip + (size_t)row  * 128 + col) =
                    make_float2(acc[mi][j].x, acc[mi][j].y);
                if (row2 < NN) *(float2*)(g_skip + (size_t)row2 * 128 + col) =
                    make_float2(acc[mi][j].z, acc[mi][j].w);
            }
        }
    }
}

// Fused CSR aggregation + softmax-norm + bias + skip + LayerNorm (warp/node)
// unroll-8 with batched prefetch for gather MLP
__global__ void __launch_bounds__(256) eagg_k(const float* __restrict__ gb,
                                              const float* __restrict__ sb,
                                              const float* __restrict__ lg,
                                              const float* __restrict__ lb,
                                              float* __restrict__ out) {
    int g = blockIdx.x * blockDim.x + threadIdx.x;
    int n = g >> 5, lane = g & 31;
    if (n >= NN) return;
    int h = lane >> 3;

    float ad_h = g_ad[n * 4 + h];

    // self loop
    float p = __expf(lrelu(g_as[n * 4 + h] + ad_h));
    float4 hv = unpack4(((const uint2*)(g_hf + (size_t)n * 64))[lane]);
    float z = p;
    float4 acc = make_float4(p * hv.x, p * hv.y, p * hv.z, p * hv.w);

    int e   = g_off[n];
    int end = g_off[n + 1];
    for (; e + 8 <= end; e += 8) {
        int s[8];
#pragma unroll
        for (int q = 0; q < 8; q++) s[q] = __ldg(g_esrc + e + q);
        float a[8];
#pragma unroll
        for (int q = 0; q < 8; q++) a[q] = __ldg(g_as + s[q] * 4 + h);
        uint2 w[8];
#pragma unroll
        for (int q = 0; q < 8; q++) w[q] = ((const uint2*)(g_hf + (size_t)s[q] * 64))[lane];
#pragma unroll
        for (int q = 0; q < 8; q++) {
            float pq = __expf(lrelu(a[q] + ad_h));
            z += pq;
            float4 hq = unpack4(w[q]);
            acc.x += pq * hq.x; acc.y += pq * hq.y;
            acc.z += pq * hq.z; acc.w += pq * hq.w;
        }
    }
    for (; e < end; e++) {
        int s0 = __ldg(g_esrc + e);
        float a0 = __ldg(g_as + s0 * 4 + h);
        float4 h0 = unpack4(((const uint2*)(g_hf + (size_t)s0 * 64))[lane]);
        float p0 = __expf(lrelu(a0 + ad_h));
        z += p0;
        acc.x += p0 * h0.x; acc.y += p0 * h0.y;
        acc.z += p0 * h0.z; acc.w += p0 * h0.w;
    }

    float inv = 1.0f / (z + 1e-16f);
    float4 sk = ((const float4*)(g_skip + (size_t)n * 128))[lane];
    float4 b1 = ((const float4*)gb)[lane];
    float4 b2 = ((const float4*)sb)[lane];
    float4 v;
    v.x = acc.x * inv + sk.x + b1.x + b2.x;
    v.y = acc.y * inv + sk.y + b1.y + b2.y;
    v.z = acc.z * inv + sk.z + b1.z + b2.z;
    v.w = acc.w * inv + sk.w + b1.w + b2.w;

    float sum = v.x + v.y + v.z + v.w;
    float sq  = v.x * v.x + v.y * v.y + v.z * v.z + v.w * v.w;
#pragma unroll
    for (int o = 16; o >= 1; o >>= 1) {
        sum += __shfl_xor_sync(0xffffffff, sum, o);
        sq  += __shfl_xor_sync(0xffffffff, sq, o);
    }
    float mu  = sum * (1.0f / 128.0f);
    float var = sq * (1.0f / 128.0f) - mu * mu;
    float invs = rsqrtf(var + 1e-5f);
    float4 gg = ((const float4*)lg)[lane];
    float4 bb = ((const float4*)lb)[lane];
    float4 o4;
    o4.x = (v.x - mu) * invs * gg.x + bb.x;
    o4.y = (v.y - mu) * invs * gg.y + bb.y;
    o4.z = (v.z - mu) * invs * gg.z + bb.z;
    o4.w = (v.w - mu) * invs * gg.w + bb.w;
    ((float4*)(out + (size_t)n * 128))[lane] = o4;
}

// ---------------- stream setup (lazy, first kernel_launch call) ----------------
struct Streams {
    cudaStream_t s1 = 0;
    cudaEvent_t  ev0 = 0, ev1 = 0, ev2 = 0;
    bool ok = false;
    Streams() {
        ok = cudaStreamCreateWithFlags(&s1, cudaStreamNonBlocking) == cudaSuccess &&
             cudaEventCreateWithFlags(&ev0, cudaEventDisableTiming) == cudaSuccess &&
             cudaEventCreateWithFlags(&ev1, cudaEventDisableTiming) == cudaSuccess &&
             cudaEventCreateWithFlags(&ev2, cudaEventDisableTiming) == cudaSuccess;
    }
};

// ---------------- launch ----------------
extern "C" void kernel_launch(void* const* d_in, const int* in_sizes, int n_in,
                              void* d_out, int out_size) {
    const float* x        = (const float*)d_in[0];
    const void*  ei       = d_in[1];
    const float* W        = (const float*)d_in[2];
    const float* att_src  = (const float*)d_in[3];
    const float* att_dst  = (const float*)d_in[4];
    const float* gat_bias = (const float*)d_in[5];
    const float* skip_W   = (const float*)d_in[6];
    const float* skip_b   = (const float*)d_in[7];
    const float* ln_g     = (const float*)d_in[8];
    const float* ln_b     = (const float*)d_in[9];
    float* out = (float*)d_out;

    int nblocks = (NN + 1023) / 1024;
    dim3 ggrid((NN + BM - 1) / BM, 2);
    const int EHALF = EE / 2;   // even
    int sc_blocks = (EHALF / 2 + 255) / 256;

    static Streams st;

    if (st.ok) {
        detect_k<<<1, 32>>>((const long long*)ei);                          // 0
        wsplit_k<<<64, 256>>>(W, skip_W);                                   // 1
        cudaEventRecord(st.ev0, 0);
        cudaStreamWaitEvent(st.s1, st.ev0, 0);
        init_k<<<(NN + 255) / 256, 256, 0, st.s1>>>();                      // 2 (side)
        gemm_bf16_k<<<ggrid, 256>>>(x, att_src, att_dst);                   // 3 (main) <- ncu slot
        hist_k<<<(EE / 2 + 255) / 256, 256, 0, st.s1>>>(ei);                // side
        scanA_k<<<nblocks, 1024, 0, st.s1>>>();
        scanB_k<<<1, 128, 0, st.s1>>>(nblocks);
        scanC_k<<<(NN + 255) / 256, 256, 0, st.s1>>>();
        cudaEventRecord(st.ev2, st.s1);
        scatter_k<<<sc_blocks, 256, 0, st.s1>>>(ei, 0, EHALF);              // side: lo half
        cudaEventRecord(st.ev1, st.s1);
        cudaStreamWaitEvent(0, st.ev2, 0);
        scatter_k<<<sc_blocks, 256>>>(ei, EHALF, EE);                       // main: hi half
        cudaStreamWaitEvent(0, st.ev1, 0);
        eagg_k<<<(NN * 32 + 255) / 256, 256>>>(gat_bias, skip_b, ln_g, ln_b, out);
    } else {
        detect_k<<<1, 32>>>((const long long*)ei);
        wsplit_k<<<64, 256>>>(W, skip_W);
        init_k<<<(NN + 255) / 256, 256>>>();
        gemm_bf16_k<<<ggrid, 256>>>(x, att_src, att_dst);
        hist_k<<<(EE / 2 + 255) / 256, 256>>>(ei);
        scanA_k<<<nblocks, 1024>>>();
        scanB_k<<<1, 128>>>(nblocks);
        scanC_k<<<(NN + 255) / 256, 256>>>();
        scatter_k<<<(EE / 2 + 255) / 256, 256>>>(ei, 0, EE);
        eagg_k<<<(NN * 32 + 255) / 256, 256>>>(gat_bias, skip_b, ln_g, ln_b, out);
    }
}

// round 13
// speedup vs baseline: 5.6072x; 1.1545x over previous
#include <cuda_runtime.h>
#include <cuda_bf16.h>
#include <cuda_fp16.h>
#include <math.h>

#define NN    100000
#define EE    1600000
#define HH    4
#define DD    128
#define BM    64
#define BK    16

// ---------------- scratch (device globals) ----------------
__device__ unsigned g_hf[NN * 64];     // h as packed fp16x2 [N][64]
__device__ float    g_skip[NN * DD];   // x @ skip_W (fp32)
__device__ unsigned g_Wf[64 * 256];    // [W | skip_W] fp16, packed k-pairs [64 kp][256 n]
__device__ float    g_as[NN * HH];
__device__ float    g_ad[NN * HH];
__device__ int      g_cnt[NN];
__device__ int      g_exc[NN];
__device__ int      g_bsum[128];
__device__ int      g_boff[128];
__device__ int      g_off[NN + 1];
__device__ int      g_cur[NN];
__device__ int      g_esrc[EE];
__device__ int      g_is64;

// ---------------- helpers ----------------
__device__ __forceinline__ float lrelu(float v) { return v > 0.0f ? v : 0.2f * v; }

__device__ __forceinline__ void mma_fp16(float4& c, const unsigned a[4],
                                         unsigned b0, unsigned b1) {
    asm volatile(
        "mma.sync.aligned.m16n8k16.row.col.f32.f16.f16.f32 "
        "{%0,%1,%2,%3}, {%4,%5,%6,%7}, {%8,%9}, {%0,%1,%2,%3};"
        : "+f"(c.x), "+f"(c.y), "+f"(c.z), "+f"(c.w)
        : "r"(a[0]), "r"(a[1]), "r"(a[2]), "r"(a[3]), "r"(b0), "r"(b1));
}

__device__ __forceinline__ unsigned pack_h2(float a, float b) {
    __half2 r = __floats2half2_rn(a, b);
    return *(unsigned*)&r;
}

__device__ __forceinline__ void cp16(unsigned* dst_smem, const unsigned* src) {
    unsigned d = (unsigned)__cvta_generic_to_shared(dst_smem);
    asm volatile("cp.async.cg.shared.global [%0], [%1], 16;" :: "r"(d), "l"(src));
}

__device__ __forceinline__ float4 unpack4(uint2 w) {
    float2 f0 = __half22float2(*(__half2*)&w.x);
    float2 f1 = __half22float2(*(__half2*)&w.y);
    return make_float4(f0.x, f0.y, f1.x, f1.y);
}

// ---------------- kernels ----------------
__global__ void detect_k(const long long* ei) {
    if (blockIdx.x == 0 && threadIdx.x == 0) {
        int ok64 = 1;
        for (int i = 0; i < 64; i++) {
            long long v = ei[i];
            if (v < 0 || v >= NN) { ok64 = 0; break; }
        }
        g_is64 = ok64;
    }
}

// pack [W | skip_W] -> fp16, k-pairs: [64 kp][256 n]
__global__ void wsplit_k(const float* __restrict__ W, const float* __restrict__ sW) {
    int i = blockIdx.x * blockDim.x + threadIdx.x;
    if (i >= 64 * 256) return;
    int kp = i >> 8, c = i & 255;
    float v0, v1;
    if (c < 128) { v0 = W[(2 * kp) * 128 + c];        v1 = W[(2 * kp + 1) * 128 + c]; }
    else         { v0 = sW[(2 * kp) * 128 + c - 128]; v1 = sW[(2 * kp + 1) * 128 + c - 128]; }
    g_Wf[i] = pack_h2(v0, v1);
}

__global__ void init_k() {
    int i = blockIdx.x * blockDim.x + threadIdx.x;
    if (i < NN) g_cnt[i] = 0;
}

// 2 edges per thread, vectorized dst loads
__global__ void hist_k(const void* __restrict__ ei) {
    int i = (blockIdx.x * blockDim.x + threadIdx.x) * 2;
    if (i >= EE) return;
    if (g_is64) {
        longlong2 v = *(const longlong2*)((const long long*)ei + EE + i);
        atomicAdd(&g_cnt[(int)v.x], 1);
        atomicAdd(&g_cnt[(int)v.y], 1);
    } else {
        int2 v = *(const int2*)((const int*)ei + EE + i);
        atomicAdd(&g_cnt[v.x], 1);
        atomicAdd(&g_cnt[v.y], 1);
    }
}

__global__ void __launch_bounds__(1024) scanA_k() {
    __shared__ int sd[1024];
    int t = threadIdx.x;
    int i = blockIdx.x * 1024 + t;
    int v = (i < NN) ? g_cnt[i] : 0;
    sd[t] = v;
    __syncthreads();
#pragma unroll
    for (int o = 1; o < 1024; o <<= 1) {
        int x = (t >= o) ? sd[t - o] : 0;
        __syncthreads();
        sd[t] += x;
        __syncthreads();
    }
    if (i < NN) g_exc[i] = sd[t] - v;
    if (t == 1023) g_bsum[blockIdx.x] = sd[t];
}

__global__ void scanB_k(int nblocks) {
    __shared__ int sd[128];
    int t = threadIdx.x;
    int v = (t < nblocks) ? g_bsum[t] : 0;
    sd[t] = v;
    __syncthreads();
#pragma unroll
    for (int o = 1; o < 128; o <<= 1) {
        int x = (t >= o) ? sd[t - o] : 0;
        __syncthreads();
        sd[t] += x;
        __syncthreads();
    }
    g_boff[t] = sd[t] - v;
}

__global__ void scanC_k() {
    int i = blockIdx.x * blockDim.x + threadIdx.x;
    if (i < NN) {
        int off = g_exc[i] + g_boff[i >> 10];
        g_off[i] = off;
        g_cur[i] = off;
    }
    if (i == 0) g_off[NN] = EE;
}

// scatter a sub-range [e0, e1) of edges; 2 edges per thread
__global__ void scatter_k(const void* __restrict__ ei, int e0, int e1) {
    int i = e0 + (blockIdx.x * blockDim.x + threadIdx.x) * 2;
    if (i >= e1) return;
    int s0, d0, s1, d1;
    if (g_is64) {
        const long long* p = (const long long*)ei;
        longlong2 sv = *(const longlong2*)(p + i);
        longlong2 dv = *(const longlong2*)(p + EE + i);
        s0 = (int)sv.x; s1 = (int)sv.y; d0 = (int)dv.x; d1 = (int)dv.y;
    } else {
        const int* p = (const int*)ei;
        int2 sv = *(const int2*)(p + i);
        int2 dv = *(const int2*)(p + EE + i);
        s0 = sv.x; s1 = sv.y; d0 = dv.x; d1 = dv.y;
    }
    g_esrc[atomicAdd(&g_cur[d0], 1)] = s0;
    if (i + 1 < e1) g_esrc[atomicAdd(&g_cur[d1], 1)] = s1;
}

// fp16 GEMM: tile M=64, N=128 per block.
// blockIdx.y = 0: h-half -> g_hf + fused att logits; 1: skip-half -> g_skip
#define XP 12    // A smem pitch in u32
#define WP 136   // B smem pitch in u32
__global__ void __launch_bounds__(256, 4) gemm_fp16_k(const float* __restrict__ x,
                                                      const float* __restrict__ asrc,
                                                      const float* __restrict__ adst) {
    __shared__ __align__(16) unsigned xs[2][BM * XP];
    __shared__ __align__(16) unsigned ws[2][8 * WP];
    int t = threadIdx.x;
    int wid = t >> 5, lane = t & 31;
    int gid = lane >> 2, tig = lane & 3;
    int wm = wid >> 2, wn = wid & 3;
    int m0 = blockIdx.x * BM;
    int half = blockIdx.y;
    int ncol0 = half * 128;

    int xrow = t >> 2;
    int xq   = t & 3;
    int wr   = t >> 5;
    int wc4  = (t & 31) * 4;

    float4 acc[2][4];
#pragma unroll
    for (int mi = 0; mi < 2; mi++)
#pragma unroll
        for (int j = 0; j < 4; j++) acc[mi][j] = make_float4(0.f, 0.f, 0.f, 0.f);

    // ---- prologue ----
    {
        cp16(&ws[0][wr * WP + wc4], &g_Wf[wr * 256 + ncol0 + wc4]);
        asm volatile("cp.async.commit_group;");
        float4 v = make_float4(0.f, 0.f, 0.f, 0.f);
        if (m0 + xrow < NN)
            v = *(const float4*)(x + (size_t)(m0 + xrow) * 128 + xq * 4);
        int b = xrow * XP + xq * 2;
        xs[0][b]     = pack_h2(v.x, v.y);
        xs[0][b + 1] = pack_h2(v.z, v.w);
        asm volatile("cp.async.wait_group 0;");
        __syncthreads();
    }

    for (int it = 0; it < 8; it++) {
        int cur = it & 1, nxt = cur ^ 1;
        float4 v;
        bool more = (it < 7);
        if (more) {
            int kp0 = ((it + 1) * BK) >> 1;
            cp16(&ws[nxt][wr * WP + wc4], &g_Wf[(kp0 + wr) * 256 + ncol0 + wc4]);
            asm volatile("cp.async.commit_group;");
            v = make_float4(0.f, 0.f, 0.f, 0.f);
            if (m0 + xrow < NN)
                v = *(const float4*)(x + (size_t)(m0 + xrow) * 128 + (it + 1) * BK + xq * 4);
        }

        unsigned ah[2][4];
#pragma unroll
        for (int mi = 0; mi < 2; mi++) {
            int rb = wm * 32 + mi * 16 + gid;
            ah[mi][0] = xs[cur][rb * XP + tig];
            ah[mi][1] = xs[cur][(rb + 8) * XP + tig];
            ah[mi][2] = xs[cur][rb * XP + tig + 4];
            ah[mi][3] = xs[cur][(rb + 8) * XP + tig + 4];
        }
#pragma unroll
        for (int j = 0; j < 4; j++) {
            int col = wn * 32 + j * 8 + gid;
            unsigned b0 = ws[cur][tig * WP + col];
            unsigned b1 = ws[cur][(tig + 4) * WP + col];
#pragma unroll
            for (int mi = 0; mi < 2; mi++)
                mma_fp16(acc[mi][j], ah[mi], b0, b1);
        }

        if (more) {
            int b = xrow * XP + xq * 2;
            xs[nxt][b]     = pack_h2(v.x, v.y);
            xs[nxt][b + 1] = pack_h2(v.z, v.w);
            asm volatile("cp.async.wait_group 0;");
            __syncthreads();
        }
    }

    if (half == 0) {
#pragma unroll
        for (int mi = 0; mi < 2; mi++) {
            int row  = m0 + wm * 32 + mi * 16 + gid;
            int row2 = row + 8;
            float ps0 = 0.f, pd0 = 0.f, ps1 = 0.f, pd1 = 0.f;
#pragma unroll
            for (int j = 0; j < 4; j++) {
                int col = wn * 32 + j * 8 + tig * 2;
                if (row  < NN) g_hf[(size_t)row  * 64 + (col >> 1)] =
                    pack_h2(acc[mi][j].x, acc[mi][j].y);
                if (row2 < NN) g_hf[(size_t)row2 * 64 + (col >> 1)] =
                    pack_h2(acc[mi][j].z, acc[mi][j].w);
                float as0 = asrc[col], as1 = asrc[col + 1];
                float ad0 = adst[col], ad1 = adst[col + 1];
                ps0 += acc[mi][j].x * as0 + acc[mi][j].y * as1;
                pd0 += acc[mi][j].x * ad0 + acc[mi][j].y * ad1;
                ps1 += acc[mi][j].z * as0 + acc[mi][j].w * as1;
                pd1 += acc[mi][j].z * ad0 + acc[mi][j].w * ad1;
            }
#pragma unroll
            for (int o = 1; o <= 2; o <<= 1) {
                ps0 += __shfl_xor_sync(0xffffffff, ps0, o);
                pd0 += __shfl_xor_sync(0xffffffff, pd0, o);
                ps1 += __shfl_xor_sync(0xffffffff, ps1, o);
                pd1 += __shfl_xor_sync(0xffffffff, pd1, o);
            }
            if (tig == 0) {
                if (row < NN)  { g_as[row * 4 + wn]  = ps0; g_ad[row * 4 + wn]  = pd0; }
                if (row2 < NN) { g_as[row2 * 4 + wn] = ps1; g_ad[row2 * 4 + wn] = pd1; }
            }
        }
    } else {
#pragma unroll
        for (int mi = 0; mi < 2; mi++) {
#pragma unroll
            for (int j = 0; j < 4; j++) {
                int col  = wn * 32 + j * 8 + tig * 2;
                int row  = m0 + wm * 32 + mi * 16 + gid;
                int row2 = row + 8;
                if (row  < NN) *(float2*)(g_skip + (size_t)row  * 128 + col) =
                    make_float2(acc[mi][j].x, acc[mi][j].y);
                if (row2 < NN) *(float2*)(g_skip + (size_t)row2 * 128 + col) =
                    make_float2(acc[mi][j].z, acc[mi][j].w);
            }
        }
    }
}

// Fused CSR aggregation + softmax-norm + bias + skip + LayerNorm (warp/node)
__global__ void __launch_bounds__(256) eagg_k(const float* __restrict__ gb,
                                              const float* __restrict__ sb,
                                              const float* __restrict__ lg,
                                              const float* __restrict__ lb,
                                              float* __restrict__ out) {
    int g = blockIdx.x * blockDim.x + threadIdx.x;
    int n = g >> 5, lane = g & 31;
    if (n >= NN) return;
    int h = lane >> 3;

    float ad_h = g_ad[n * 4 + h];

    // self loop
    float p = __expf(lrelu(g_as[n * 4 + h] + ad_h));
    float4 hv = unpack4(((const uint2*)(g_hf + (size_t)n * 64))[lane]);
    float z = p;
    float4 acc = make_float4(p * hv.x, p * hv.y, p * hv.z, p * hv.w);

    int e   = g_off[n];
    int end = g_off[n + 1];
    for (; e + 8 <= end; e += 8) {
        int s[8];
#pragma unroll
        for (int q = 0; q < 8; q++) s[q] = __ldg(g_esrc + e + q);
        float a[8];
#pragma unroll
        for (int q = 0; q < 8; q++) a[q] = __ldg(g_as + s[q] * 4 + h);
        uint2 w[8];
#pragma unroll
        for (int q = 0; q < 8; q++) w[q] = ((const uint2*)(g_hf + (size_t)s[q] * 64))[lane];
#pragma unroll
        for (int q = 0; q < 8; q++) {
            float pq = __expf(lrelu(a[q] + ad_h));
            z += pq;
            float4 hq = unpack4(w[q]);
            acc.x += pq * hq.x; acc.y += pq * hq.y;
            acc.z += pq * hq.z; acc.w += pq * hq.w;
        }
    }
    for (; e < end; e++) {
        int s0 = __ldg(g_esrc + e);
        float a0 = __ldg(g_as + s0 * 4 + h);
        float4 h0 = unpack4(((const uint2*)(g_hf + (size_t)s0 * 64))[lane]);
        float p0 = __expf(lrelu(a0 + ad_h));
        z += p0;
        acc.x += p0 * h0.x; acc.y += p0 * h0.y;
        acc.z += p0 * h0.z; acc.w += p0 * h0.w;
    }

    float inv = 1.0f / (z + 1e-16f);
    float4 sk = ((const float4*)(g_skip + (size_t)n * 128))[lane];
    float4 b1 = ((const float4*)gb)[lane];
    float4 b2 = ((const float4*)sb)[lane];
    float4 v;
    v.x = acc.x * inv + sk.x + b1.x + b2.x;
    v.y = acc.y * inv + sk.y + b1.y + b2.y;
    v.z = acc.z * inv + sk.z + b1.z + b2.z;
    v.w = acc.w * inv + sk.w + b1.w + b2.w;

    float sum = v.x + v.y + v.z + v.w;
    float sq  = v.x * v.x + v.y * v.y + v.z * v.z + v.w * v.w;
#pragma unroll
    for (int o = 16; o >= 1; o >>= 1) {
        sum += __shfl_xor_sync(0xffffffff, sum, o);
        sq  += __shfl_xor_sync(0xffffffff, sq, o);
    }
    float mu  = sum * (1.0f / 128.0f);
    float var = sq * (1.0f / 128.0f) - mu * mu;
    float invs = rsqrtf(var + 1e-5f);
    float4 gg = ((const float4*)lg)[lane];
    float4 bb = ((const float4*)lb)[lane];
    float4 o4;
    o4.x = (v.x - mu) * invs * gg.x + bb.x;
    o4.y = (v.y - mu) * invs * gg.y + bb.y;
    o4.z = (v.z - mu) * invs * gg.z + bb.z;
    o4.w = (v.w - mu) * invs * gg.w + bb.w;
    ((float4*)(out + (size_t)n * 128))[lane] = o4;
}

// ---------------- stream setup (lazy, first kernel_launch call) ----------------
struct Streams {
    cudaStream_t s1 = 0;
    cudaEvent_t  ev0 = 0, ev1 = 0, ev2 = 0;
    bool ok = false;
    Streams() {
        ok = cudaStreamCreateWithFlags(&s1, cudaStreamNonBlocking) == cudaSuccess &&
             cudaEventCreateWithFlags(&ev0, cudaEventDisableTiming) == cudaSuccess &&
             cudaEventCreateWithFlags(&ev1, cudaEventDisableTiming) == cudaSuccess &&
             cudaEventCreateWithFlags(&ev2, cudaEventDisableTiming) == cudaSuccess;
    }
};

// ---------------- launch ----------------
extern "C" void kernel_launch(void* const* d_in, const int* in_sizes, int n_in,
                              void* d_out, int out_size) {
    const float* x        = (const float*)d_in[0];
    const void*  ei       = d_in[1];
    const float* W        = (const float*)d_in[2];
    const float* att_src  = (const float*)d_in[3];
    const float* att_dst  = (const float*)d_in[4];
    const float* gat_bias = (const float*)d_in[5];
    const float* skip_W   = (const float*)d_in[6];
    const float* skip_b   = (const float*)d_in[7];
    const float* ln_g     = (const float*)d_in[8];
    const float* ln_b     = (const float*)d_in[9];
    float* out = (float*)d_out;

    int nblocks = (NN + 1023) / 1024;
    dim3 ggrid((NN + BM - 1) / BM, 2);
    const int EHALF = EE / 2;
    int sc_blocks = (EHALF / 2 + 255) / 256;

    static Streams st;

    if (st.ok) {
        detect_k<<<1, 32>>>((const long long*)ei);                          // 0
        wsplit_k<<<64, 256>>>(W, skip_W);                                   // 1
        cudaEventRecord(st.ev0, 0);
        cudaStreamWaitEvent(st.s1, st.ev0, 0);
        init_k<<<(NN + 255) / 256, 256, 0, st.s1>>>();                      // 2 (side)
        gemm_fp16_k<<<ggrid, 256>>>(x, att_src, att_dst);                   // 3 (main) <- ncu slot
        hist_k<<<(EE / 2 + 255) / 256, 256, 0, st.s1>>>(ei);                // side
        scanA_k<<<nblocks, 1024, 0, st.s1>>>();
        scanB_k<<<1, 128, 0, st.s1>>>(nblocks);
        scanC_k<<<(NN + 255) / 256, 256, 0, st.s1>>>();
        cudaEventRecord(st.ev2, st.s1);
        scatter_k<<<sc_blocks, 256, 0, st.s1>>>(ei, 0, EHALF);              // side: lo half
        cudaEventRecord(st.ev1, st.s1);
        cudaStreamWaitEvent(0, st.ev2, 0);
        scatter_k<<<sc_blocks, 256>>>(ei, EHALF, EE);                       // main: hi half
        cudaStreamWaitEvent(0, st.ev1, 0);
        eagg_k<<<(NN * 32 + 255) / 256, 256>>>(gat_bias, skip_b, ln_g, ln_b, out);
    } else {
        detect_k<<<1, 32>>>((const long long*)ei);
        wsplit_k<<<64, 256>>>(W, skip_W);
        init_k<<<(NN + 255) / 256, 256>>>();
        gemm_fp16_k<<<ggrid, 256>>>(x, att_src, att_dst);
        hist_k<<<(EE / 2 + 255) / 256, 256>>>(ei);
        scanA_k<<<nblocks, 1024>>>();
        scanB_k<<<1, 128>>>(nblocks);
        scanC_k<<<(NN + 255) / 256, 256>>>();
        scatter_k<<<(EE / 2 + 255) / 256, 256>>>(ei, 0, EE);
        eagg_k<<<(NN * 32 + 255) / 256, 256>>>(gat_bias, skip_b, ln_g, ln_b, out);
    }
}

// round 14
// speedup vs baseline: 5.6723x; 1.0116x over previous
#include <cuda_runtime.h>
#include <cuda_bf16.h>
#include <cuda_fp16.h>
#include <math.h>

#define NN    100000
#define EE    1600000
#define HH    4
#define DD    128
#define BM    64
#define BK    16

// ---------------- scratch (device globals) ----------------
__device__ unsigned g_xf[NN * 64];     // x as packed fp16x2 [N][64]
__device__ unsigned g_hf[NN * 64];     // h as packed fp16x2 [N][64]
__device__ unsigned g_skipf[NN * 64];  // skip as packed fp16x2 [N][64]
__device__ unsigned g_Wf[64 * 256];    // [W | skip_W] fp16, packed k-pairs [64 kp][256 n]
__device__ float    g_as[NN * HH];
__device__ float    g_ad[NN * HH];
__device__ int      g_cnt[NN];
__device__ int      g_exc[NN];
__device__ int      g_bsum[128];
__device__ int      g_boff[128];
__device__ int      g_off[NN + 1];
__device__ int      g_cur[NN];
__device__ int      g_esrc[EE];
__device__ int      g_is64;

// ---------------- helpers ----------------
__device__ __forceinline__ float lrelu(float v) { return v > 0.0f ? v : 0.2f * v; }

__device__ __forceinline__ void mma_fp16(float4& c, const unsigned a[4],
                                         unsigned b0, unsigned b1) {
    asm volatile(
        "mma.sync.aligned.m16n8k16.row.col.f32.f16.f16.f32 "
        "{%0,%1,%2,%3}, {%4,%5,%6,%7}, {%8,%9}, {%0,%1,%2,%3};"
        : "+f"(c.x), "+f"(c.y), "+f"(c.z), "+f"(c.w)
        : "r"(a[0]), "r"(a[1]), "r"(a[2]), "r"(a[3]), "r"(b0), "r"(b1));
}

__device__ __forceinline__ void ldsm_x4(unsigned r[4], const unsigned* smem_ptr) {
    unsigned addr = (unsigned)__cvta_generic_to_shared(smem_ptr);
    asm volatile("ldmatrix.sync.aligned.m8n8.x4.shared.b16 {%0,%1,%2,%3}, [%4];"
                 : "=r"(r[0]), "=r"(r[1]), "=r"(r[2]), "=r"(r[3]) : "r"(addr));
}

__device__ __forceinline__ unsigned pack_h2(float a, float b) {
    __half2 r = __floats2half2_rn(a, b);
    return *(unsigned*)&r;
}

__device__ __forceinline__ void cp16(unsigned* dst_smem, const unsigned* src) {
    unsigned d = (unsigned)__cvta_generic_to_shared(dst_smem);
    asm volatile("cp.async.cg.shared.global [%0], [%1], 16;" :: "r"(d), "l"(src));
}

__device__ __forceinline__ float4 unpack4(uint2 w) {
    float2 f0 = __half22float2(*(__half2*)&w.x);
    float2 f1 = __half22float2(*(__half2*)&w.y);
    return make_float4(f0.x, f0.y, f1.x, f1.y);
}

// ---------------- kernels ----------------
__global__ void detect_k(const long long* ei) {
    if (blockIdx.x == 0 && threadIdx.x == 0) {
        int ok64 = 1;
        for (int i = 0; i < 64; i++) {
            long long v = ei[i];
            if (v < 0 || v >= NN) { ok64 = 0; break; }
        }
        g_is64 = ok64;
    }
}

// pack [W | skip_W] -> fp16, k-pairs: [64 kp][256 n]
__global__ void wsplit_k(const float* __restrict__ W, const float* __restrict__ sW) {
    int i = blockIdx.x * blockDim.x + threadIdx.x;
    if (i >= 64 * 256) return;
    int kp = i >> 8, c = i & 255;
    float v0, v1;
    if (c < 128) { v0 = W[(2 * kp) * 128 + c];        v1 = W[(2 * kp + 1) * 128 + c]; }
    else         { v0 = sW[(2 * kp) * 128 + c - 128]; v1 = sW[(2 * kp + 1) * 128 + c - 128]; }
    g_Wf[i] = pack_h2(v0, v1);
}

// x -> packed fp16x2
__global__ void xhalf_k(const float* __restrict__ x) {
    int i = blockIdx.x * blockDim.x + threadIdx.x;
    if (i >= NN * 32) return;
    float4 v = ((const float4*)x)[i];
    ((uint2*)g_xf)[i] = make_uint2(pack_h2(v.x, v.y), pack_h2(v.z, v.w));
}

__global__ void init_k() {
    int i = blockIdx.x * blockDim.x + threadIdx.x;
    if (i < NN) g_cnt[i] = 0;
}

// 2 edges per thread, vectorized dst loads
__global__ void hist_k(const void* __restrict__ ei) {
    int i = (blockIdx.x * blockDim.x + threadIdx.x) * 2;
    if (i >= EE) return;
    if (g_is64) {
        longlong2 v = *(const longlong2*)((const long long*)ei + EE + i);
        atomicAdd(&g_cnt[(int)v.x], 1);
        atomicAdd(&g_cnt[(int)v.y], 1);
    } else {
        int2 v = *(const int2*)((const int*)ei + EE + i);
        atomicAdd(&g_cnt[v.x], 1);
        atomicAdd(&g_cnt[v.y], 1);
    }
}

__global__ void __launch_bounds__(1024) scanA_k() {
    __shared__ int sd[1024];
    int t = threadIdx.x;
    int i = blockIdx.x * 1024 + t;
    int v = (i < NN) ? g_cnt[i] : 0;
    sd[t] = v;
    __syncthreads();
#pragma unroll
    for (int o = 1; o < 1024; o <<= 1) {
        int x = (t >= o) ? sd[t - o] : 0;
        __syncthreads();
        sd[t] += x;
        __syncthreads();
    }
    if (i < NN) g_exc[i] = sd[t] - v;
    if (t == 1023) g_bsum[blockIdx.x] = sd[t];
}

__global__ void scanB_k(int nblocks) {
    __shared__ int sd[128];
    int t = threadIdx.x;
    int v = (t < nblocks) ? g_bsum[t] : 0;
    sd[t] = v;
    __syncthreads();
#pragma unroll
    for (int o = 1; o < 128; o <<= 1) {
        int x = (t >= o) ? sd[t - o] : 0;
        __syncthreads();
        sd[t] += x;
        __syncthreads();
    }
    g_boff[t] = sd[t] - v;
}

__global__ void scanC_k() {
    int i = blockIdx.x * blockDim.x + threadIdx.x;
    if (i < NN) {
        int off = g_exc[i] + g_boff[i >> 10];
        g_off[i] = off;
        g_cur[i] = off;
    }
    if (i == 0) g_off[NN] = EE;
}

// scatter a sub-range [e0, e1) of edges; 2 edges per thread
__global__ void scatter_k(const void* __restrict__ ei, int e0, int e1) {
    int i = e0 + (blockIdx.x * blockDim.x + threadIdx.x) * 2;
    if (i >= e1) return;
    int s0, d0, s1, d1;
    if (g_is64) {
        const long long* p = (const long long*)ei;
        longlong2 sv = *(const longlong2*)(p + i);
        longlong2 dv = *(const longlong2*)(p + EE + i);
        s0 = (int)sv.x; s1 = (int)sv.y; d0 = (int)dv.x; d1 = (int)dv.y;
    } else {
        const int* p = (const int*)ei;
        int2 sv = *(const int2*)(p + i);
        int2 dv = *(const int2*)(p + EE + i);
        s0 = sv.x; s1 = sv.y; d0 = dv.x; d1 = dv.y;
    }
    g_esrc[atomicAdd(&g_cur[d0], 1)] = s0;
    if (i + 1 < e1) g_esrc[atomicAdd(&g_cur[d1], 1)] = s1;
}

// fp16 GEMM: tile M=64, N=128 per block; A and W staged purely via cp.async.
// A-fragments via ldmatrix.x4.
// blockIdx.y = 0: h-half -> g_hf + fused att logits; 1: skip-half -> g_skipf
#define XP 12    // A smem pitch in u32 (48B: 16B-aligned, LDSM conflict-free)
#define WP 136   // B smem pitch in u32
__global__ void __launch_bounds__(256, 4) gemm_fp16_k(const float* __restrict__ asrc,
                                                      const float* __restrict__ adst) {
    __shared__ __align__(16) unsigned xs[2][BM * XP];
    __shared__ __align__(16) unsigned ws[2][8 * WP];
    int t = threadIdx.x;
    int wid = t >> 5, lane = t & 31;
    int gid = lane >> 2, tig = lane & 3;
    int wm = wid >> 2, wn = wid & 3;
    int m0 = blockIdx.x * BM;
    int half = blockIdx.y;
    int ncol0 = half * 128;

    int wr  = t >> 5;            // W staging: kp row 0..7
    int wc4 = (t & 31) * 4;      // u32 col (16B chunk)
    int arow = t >> 1;           // A staging: row 0..63 (t<128)
    int ach  = (t & 1) * 4;      // chunk u32 offset
    bool astage = t < 128;
    int arow_g = m0 + arow; if (arow_g >= NN) arow_g = NN - 1;
    const unsigned* abase = g_xf + (size_t)arow_g * 64 + ach;

    float4 acc[2][4];
#pragma unroll
    for (int mi = 0; mi < 2; mi++)
#pragma unroll
        for (int j = 0; j < 4; j++) acc[mi][j] = make_float4(0.f, 0.f, 0.f, 0.f);

    // ---- prologue: stage k-tile 0 ----
    {
        cp16(&ws[0][wr * WP + wc4], &g_Wf[wr * 256 + ncol0 + wc4]);
        if (astage) cp16(&xs[0][arow * XP + ach], abase);
        asm volatile("cp.async.commit_group;");
        asm volatile("cp.async.wait_group 0;");
        __syncthreads();
    }

    for (int it = 0; it < 8; it++) {
        int cur = it & 1, nxt = cur ^ 1;
        bool more = (it < 7);
        if (more) {
            int kp0 = (it + 1) * 8;
            cp16(&ws[nxt][wr * WP + wc4], &g_Wf[(kp0 + wr) * 256 + ncol0 + wc4]);
            if (astage) cp16(&xs[nxt][arow * XP + ach], abase + kp0);
            asm volatile("cp.async.commit_group;");
        }

        unsigned ah[2][4];
#pragma unroll
        for (int mi = 0; mi < 2; mi++) {
            int rb0 = wm * 32 + mi * 16;
            ldsm_x4(ah[mi], &xs[cur][(rb0 + (lane & 15)) * XP + (lane >> 4) * 4]);
        }
#pragma unroll
        for (int j = 0; j < 4; j++) {
            int col = wn * 32 + j * 8 + gid;
            unsigned b0 = ws[cur][tig * WP + col];
            unsigned b1 = ws[cur][(tig + 4) * WP + col];
            mma_fp16(acc[0][j], ah[0], b0, b1);
            mma_fp16(acc[1][j], ah[1], b0, b1);
        }

        if (more) {
            asm volatile("cp.async.wait_group 0;");
            __syncthreads();
        }
    }

    if (half == 0) {
#pragma unroll
        for (int mi = 0; mi < 2; mi++) {
            int row  = m0 + wm * 32 + mi * 16 + gid;
            int row2 = row + 8;
            float ps0 = 0.f, pd0 = 0.f, ps1 = 0.f, pd1 = 0.f;
#pragma unroll
            for (int j = 0; j < 4; j++) {
                int col = wn * 32 + j * 8 + tig * 2;
                if (row  < NN) g_hf[(size_t)row  * 64 + (col >> 1)] =
                    pack_h2(acc[mi][j].x, acc[mi][j].y);
                if (row2 < NN) g_hf[(size_t)row2 * 64 + (col >> 1)] =
                    pack_h2(acc[mi][j].z, acc[mi][j].w);
                float as0 = asrc[col], as1 = asrc[col + 1];
                float ad0 = adst[col], ad1 = adst[col + 1];
                ps0 += acc[mi][j].x * as0 + acc[mi][j].y * as1;
                pd0 += acc[mi][j].x * ad0 + acc[mi][j].y * ad1;
                ps1 += acc[mi][j].z * as0 + acc[mi][j].w * as1;
                pd1 += acc[mi][j].z * ad0 + acc[mi][j].w * ad1;
            }
#pragma unroll
            for (int o = 1; o <= 2; o <<= 1) {
                ps0 += __shfl_xor_sync(0xffffffff, ps0, o);
                pd0 += __shfl_xor_sync(0xffffffff, pd0, o);
                ps1 += __shfl_xor_sync(0xffffffff, ps1, o);
                pd1 += __shfl_xor_sync(0xffffffff, pd1, o);
            }
            if (tig == 0) {
                if (row < NN)  { g_as[row * 4 + wn]  = ps0; g_ad[row * 4 + wn]  = pd0; }
                if (row2 < NN) { g_as[row2 * 4 + wn] = ps1; g_ad[row2 * 4 + wn] = pd1; }
            }
        }
    } else {
#pragma unroll
        for (int mi = 0; mi < 2; mi++) {
#pragma unroll
            for (int j = 0; j < 4; j++) {
                int col  = wn * 32 + j * 8 + tig * 2;
                int row  = m0 + wm * 32 + mi * 16 + gid;
                int row2 = row + 8;
                if (row  < NN) g_skipf[(size_t)row  * 64 + (col >> 1)] =
                    pack_h2(acc[mi][j].x, acc[mi][j].y);
                if (row2 < NN) g_skipf[(size_t)row2 * 64 + (col >> 1)] =
                    pack_h2(acc[mi][j].z, acc[mi][j].w);
            }
        }
    }
}

// Fused CSR aggregation + softmax-norm + bias + skip + LayerNorm (warp/node)
__global__ void __launch_bounds__(256) eagg_k(const float* __restrict__ gb,
                                              const float* __restrict__ sb,
                                              const float* __restrict__ lg,
                                              const float* __restrict__ lb,
                                              float* __restrict__ out) {
    int g = blockIdx.x * blockDim.x + threadIdx.x;
    int n = g >> 5, lane = g & 31;
    if (n >= NN) return;
    int h = lane >> 3;

    float ad_h = g_ad[n * 4 + h];

    // self loop
    float p = __expf(lrelu(g_as[n * 4 + h] + ad_h));
    float4 hv = unpack4(((const uint2*)(g_hf + (size_t)n * 64))[lane]);
    float z = p;
    float4 acc = make_float4(p * hv.x, p * hv.y, p * hv.z, p * hv.w);

    int e   = g_off[n];
    int end = g_off[n + 1];
    for (; e + 8 <= end; e += 8) {
        int s[8];
#pragma unroll
        for (int q = 0; q < 8; q++) s[q] = __ldg(g_esrc + e + q);
        float a[8];
#pragma unroll
        for (int q = 0; q < 8; q++) a[q] = __ldg(g_as + s[q] * 4 + h);
        uint2 w[8];
#pragma unroll
        for (int q = 0; q < 8; q++) w[q] = ((const uint2*)(g_hf + (size_t)s[q] * 64))[lane];
#pragma unroll
        for (int q = 0; q < 8; q++) {
            float pq = __expf(lrelu(a[q] + ad_h));
            z += pq;
            float4 hq = unpack4(w[q]);
            acc.x += pq * hq.x; acc.y += pq * hq.y;
            acc.z += pq * hq.z; acc.w += pq * hq.w;
        }
    }
    for (; e < end; e++) {
        int s0 = __ldg(g_esrc + e);
        float a0 = __ldg(g_as + s0 * 4 + h);
        float4 h0 = unpack4(((const uint2*)(g_hf + (size_t)s0 * 64))[lane]);
        float p0 = __expf(lrelu(a0 + ad_h));
        z += p0;
        acc.x += p0 * h0.x; acc.y += p0 * h0.y;
        acc.z += p0 * h0.z; acc.w += p0 * h0.w;
    }

    float inv = 1.0f / (z + 1e-16f);
    float4 sk = unpack4(((const uint2*)(g_skipf + (size_t)n * 64))[lane]);
    float4 b1 = ((const float4*)gb)[lane];
    float4 b2 = ((const float4*)sb)[lane];
    float4 v;
    v.x = acc.x * inv + sk.x + b1.x + b2.x;
    v.y = acc.y * inv + sk.y + b1.y + b2.y;
    v.z = acc.z * inv + sk.z + b1.z + b2.z;
    v.w = acc.w * inv + sk.w + b1.w + b2.w;

    float sum = v.x + v.y + v.z + v.w;
    float sq  = v.x * v.x + v.y * v.y + v.z * v.z + v.w * v.w;
#pragma unroll
    for (int o = 16; o >= 1; o >>= 1) {
        sum += __shfl_xor_sync(0xffffffff, sum, o);
        sq  += __shfl_xor_sync(0xffffffff, sq, o);
    }
    float mu  = sum * (1.0f / 128.0f);
    float var = sq * (1.0f / 128.0f) - mu * mu;
    float invs = rsqrtf(var + 1e-5f);
    float4 gg = ((const float4*)lg)[lane];
    float4 bb = ((const float4*)lb)[lane];
    float4 o4;
    o4.x = (v.x - mu) * invs * gg.x + bb.x;
    o4.y = (v.y - mu) * invs * gg.y + bb.y;
    o4.z = (v.z - mu) * invs * gg.z + bb.z;
    o4.w = (v.w - mu) * invs * gg.w + bb.w;
    ((float4*)(out + (size_t)n * 128))[lane] = o4;
}

// ---------------- stream setup (lazy, first kernel_launch call) ----------------
struct Streams {
    cudaStream_t s1 = 0;
    cudaEvent_t  ev0 = 0, ev1 = 0, ev2 = 0;
    bool ok = false;
    Streams() {
        ok = cudaStreamCreateWithFlags(&s1, cudaStreamNonBlocking) == cudaSuccess &&
             cudaEventCreateWithFlags(&ev0, cudaEventDisableTiming) == cudaSuccess &&
             cudaEventCreateWithFlags(&ev1, cudaEventDisableTiming) == cudaSuccess &&
             cudaEventCreateWithFlags(&ev2, cudaEventDisableTiming) == cudaSuccess;
    }
};

// ---------------- launch ----------------
extern "C" void kernel_launch(void* const* d_in, const int* in_sizes, int n_in,
                              void* d_out, int out_size) {
    const float* x        = (const float*)d_in[0];
    const void*  ei       = d_in[1];
    const float* W        = (const float*)d_in[2];
    const float* att_src  = (const float*)d_in[3];
    const float* att_dst  = (const float*)d_in[4];
    const float* gat_bias = (const float*)d_in[5];
    const float* skip_W   = (const float*)d_in[6];
    const float* skip_b   = (const float*)d_in[7];
    const float* ln_g     = (const float*)d_in[8];
    const float* ln_b     = (const float*)d_in[9];
    float* out = (float*)d_out;

    int nblocks = (NN + 1023) / 1024;
    dim3 ggrid((NN + BM - 1) / BM, 2);
    const int EHALF = EE / 2;
    int sc_blocks = (EHALF / 2 + 255) / 256;

    static Streams st;

    if (st.ok) {
        detect_k<<<1, 32>>>((const long long*)ei);
        cudaEventRecord(st.ev0, 0);
        cudaStreamWaitEvent(st.s1, st.ev0, 0);
        // side stream: CSR build
        init_k<<<(NN + 255) / 256, 256, 0, st.s1>>>();
        hist_k<<<(EE / 2 + 255) / 256, 256, 0, st.s1>>>(ei);
        scanA_k<<<nblocks, 1024, 0, st.s1>>>();
        scanB_k<<<1, 128, 0, st.s1>>>(nblocks);
        scanC_k<<<(NN + 255) / 256, 256, 0, st.s1>>>();
        cudaEventRecord(st.ev2, st.s1);
        scatter_k<<<sc_blocks, 256, 0, st.s1>>>(ei, 0, EHALF);
        cudaEventRecord(st.ev1, st.s1);
        // main stream: prep + GEMM
        wsplit_k<<<64, 256>>>(W, skip_W);
        xhalf_k<<<(NN * 32 + 255) / 256, 256>>>(x);
        gemm_fp16_k<<<ggrid, 256>>>(att_src, att_dst);
        cudaStreamWaitEvent(0, st.ev2, 0);
        scatter_k<<<sc_blocks, 256>>>(ei, EHALF, EE);
        cudaStreamWaitEvent(0, st.ev1, 0);
        eagg_k<<<(NN * 32 + 255) / 256, 256>>>(gat_bias, skip_b, ln_g, ln_b, out);
    } else {
        detect_k<<<1, 32>>>((const long long*)ei);
        wsplit_k<<<64, 256>>>(W, skip_W);
        xhalf_k<<<(NN * 32 + 255) / 256, 256>>>(x);
        init_k<<<(NN + 255) / 256, 256>>>();
        gemm_fp16_k<<<ggrid, 256>>>(att_src, att_dst);
        hist_k<<<(EE / 2 + 255) / 256, 256>>>(ei);
        scanA_k<<<nblocks, 1024>>>();
        scanB_k<<<1, 128>>>(nblocks);
        scanC_k<<<(NN + 255) / 256, 256>>>();
        scatter_k<<<(EE / 2 + 255) / 256, 256>>>(ei, 0, EE);
        eagg_k<<<(NN * 32 + 255) / 256, 256>>>(gat_bias, skip_b, ln_g, ln_b, out);
    }
}